// round 7
// baseline (speedup 1.0000x reference)
#include <cuda_runtime.h>
#include <cuda_bf16.h>
#include <math.h>
#include <limits.h>

// Problem constants
#define NB    4
#define LL    4096
#define DD    1024
#define HH    16
#define EE    64
#define BB    64          // NB*HH
#define CC    256
#define BITS  32
#define KM_ITERS 10
#define MM    16384       // NB*LL
#define TEMP_F 0.125f
#define KC    248         // Eigen mt-heuristic: l1=16K default, mr=12, nr=4 -> 248

// ---------------- scratch (__device__ globals; no allocation allowed) ----------------
__device__ float    g_q[(size_t)BB * LL * EE];
__device__ float    g_k[(size_t)BB * LL * EE];
__device__ float    g_v[(size_t)BB * LL * EE];
__device__ unsigned g_codes[BB * LL];
__device__ unsigned g_cent[BB * CC];
__device__ int      g_histc[BB * CC];
__device__ int      g_histb[BB * CC * BITS];
__device__ int      g_assign[BB * LL];
__device__ int      g_cnt[BB * CC];
__device__ float    g_qc[(size_t)BB * CC * EE];
__device__ float    g_scores[(size_t)BB * CC * LL];     // 268 MB
__device__ float    g_vc[(size_t)BB * CC * EE];
__device__ float    g_gat[(size_t)MM * DD];

// ---------------- generic fp32 GEMM body: C = A[16384x1024] * W[1024x1024] + bias ----------------
// Eigen gebp emulation: K split into panels of KC=248 (last 32); each panel is an
// ascending-k FMA chain from zero; panels folded sequentially with one f32 add each:
// C = ((((P1+P2)+P3)+P4)+P5.
// MODE 0: plain row-major output.  MODE 1: QKV remap to [b= n*16+h][l][e].
template<int MODE>
__device__ __forceinline__ void gemm_body(const float* __restrict__ A,
                                          const float* __restrict__ W,
                                          const float* __restrict__ bias,
                                          float* __restrict__ out)
{
    const int K = 1024, N = 1024;
    const int Mrow = blockIdx.y * 64;
    const int Ncol = blockIdx.x * 128;
    __shared__ float As[8][68];
    __shared__ float Ws[8][132];
    const int tid = threadIdx.x;
    const int tx = tid % 16, ty = tid / 16;   // tx -> 8 cols, ty -> 4 rows
    const int arow = tid / 4;                 // 0..63
    const int acol = (tid % 4) * 2;           // 0,2,4,6
    const int wrow = tid / 32;                // 0..7
    const int wcol = (tid % 32) * 4;

    float c_[4][8], t_[4][8];
#pragma unroll
    for (int i = 0; i < 4; i++)
#pragma unroll
        for (int j = 0; j < 8; j++) { c_[i][j] = 0.f; t_[i][j] = 0.f; }

    for (int kt = 0; kt < K; kt += 8) {
        {
            float2 av = *(const float2*)&A[(size_t)(Mrow + arow) * K + kt + acol];
            As[acol + 0][arow] = av.x;
            As[acol + 1][arow] = av.y;
        }
        {
            float4 wv = *(const float4*)&W[(size_t)(kt + wrow) * N + Ncol + wcol];
            *(float4*)&Ws[wrow][wcol] = wv;
        }
        __syncthreads();
#pragma unroll
        for (int kk = 0; kk < 8; kk++) {
            float a[4], b[8];
#pragma unroll
            for (int i = 0; i < 4; i++) a[i] = As[kk][ty * 4 + i];
#pragma unroll
            for (int j = 0; j < 8; j++) b[j] = Ws[kk][tx * 8 + j];
#pragma unroll
            for (int i = 0; i < 4; i++)
#pragma unroll
                for (int j = 0; j < 8; j++)
                    t_[i][j] = fmaf(a[i], b[j], t_[i][j]);
        }
        __syncthreads();
        const int kend = kt + 8;
        if ((kend % KC) == 0 || kend == K) {   // panel boundary: fold t into c, reset t
#pragma unroll
            for (int i = 0; i < 4; i++)
#pragma unroll
                for (int j = 0; j < 8; j++) {
                    c_[i][j] = __fadd_rn(c_[i][j], t_[i][j]);
                    t_[i][j] = 0.f;
                }
        }
    }
#pragma unroll
    for (int i = 0; i < 4; i++) {
        int m = Mrow + ty * 4 + i;
#pragma unroll
        for (int j = 0; j < 8; j++) {
            int col = Ncol + tx * 8 + j;
            float val = c_[i][j] + bias[col];
            if (MODE == 1) {
                int n = m >> 12, l = m & 4095, h = col >> 6, e = col & 63;
                out[(((size_t)(n * 16 + h)) * 4096 + l) * 64 + e] = val;
            } else {
                out[(size_t)m * 1024 + col] = val;
            }
        }
    }
}

__global__ void __launch_bounds__(256) gemm_qkv(const float* __restrict__ A,
                                                const float* __restrict__ Wq,
                                                const float* __restrict__ Wk,
                                                const float* __restrict__ Wv,
                                                const float* __restrict__ bq,
                                                const float* __restrict__ bk,
                                                const float* __restrict__ bv)
{
    const float* W; const float* bias; float* out;
    if (blockIdx.z == 0)      { W = Wq; bias = bq; out = g_q; }
    else if (blockIdx.z == 1) { W = Wk; bias = bk; out = g_k; }
    else                      { W = Wv; bias = bv; out = g_v; }
    gemm_body<1>(A, W, bias, out);
}

__global__ void __launch_bounds__(256) gemm_out(const float* __restrict__ W,
                                                const float* __restrict__ bias,
                                                float* __restrict__ out)
{
    gemm_body<0>(g_gat, W, bias, out);
}

// ---------------- codes = pack(q @ planes > 0) ----------------
// K=64 < kc: single ascending FMA chain (Eigen NEON vfma). Rounds 2/4 showed
// fma vs mul/add are bit-equivalent here.
__global__ void __launch_bounds__(256) codes_kernel(const float* __restrict__ planes)
{
    __shared__ float pl[64 * 32];
    const int tid = threadIdx.x;
    for (int i = tid; i < 2048; i += 256) pl[i] = planes[i];
    __syncthreads();
    const int warp = tid / 32, lane = tid % 32;
    const int rowBase = (blockIdx.x * 8 + warp) * 16;
    for (int r = 0; r < 16; r++) {
        const int row = rowBase + r;
        const float* qrow = &g_q[(size_t)row * 64];
        float s = 0.f;
#pragma unroll
        for (int e = 0; e < 64; e++)
            s = fmaf(__ldg(&qrow[e]), pl[e * 32 + lane], s);
        unsigned w = __ballot_sync(0xffffffffu, s > 0.f);
        if (lane == 0) g_codes[row] = w;
    }
}

// ---------------- centroid init (+ zero hist / cnt) ----------------
__global__ void init_cent()
{
    const int b = blockIdx.x, c = threadIdx.x;
    // EXACT floor of linspace(0, L-1, C): c * 4095/255 = 273c/17, integer floor.
    int idx = (273 * c) / 17;
    g_cent[b * CC + c] = g_codes[b * LL + idx];
    g_histc[b * CC + c] = 0;
    g_cnt[b * CC + c] = 0;
#pragma unroll
    for (int bit = 0; bit < BITS; bit++) g_histb[(b * CC + c) * BITS + bit] = 0;
}

// ---------------- k-means assignment (+histogram or final-assign) ----------------
__global__ void __launch_bounds__(256) kmeans_assign(int final_pass)
{
    __shared__ unsigned scent[CC];
    __shared__ int shc[CC];
    __shared__ int shb[CC * BITS];
    const int b = blockIdx.y;
    const int tid = threadIdx.x;
    scent[tid] = g_cent[b * CC + tid];
    if (!final_pass) {
        shc[tid] = 0;
        for (int i = tid; i < CC * BITS; i += 256) shb[i] = 0;
    }
    __syncthreads();
    const int p0 = blockIdx.x * 1024;
    for (int p = p0 + tid; p < p0 + 1024; p += 256) {
        const unsigned w = g_codes[b * LL + p];
        int best = INT_MAX;
#pragma unroll 16
        for (int c = 0; c < CC; c++) {
            int d = __popc(w ^ scent[c]);
            best = min(best, (d << 8) | c);
        }
        const int bc = best & 255;
        if (final_pass) {
            g_assign[b * LL + p] = bc;
            atomicAdd(&g_cnt[b * CC + bc], 1);
        } else {
            atomicAdd(&shc[bc], 1);
            unsigned ww = w;
            while (ww) {
                int bit = __ffs(ww) - 1;
                ww &= ww - 1;
                atomicAdd(&shb[bc * BITS + bit], 1);
            }
        }
    }
    if (!final_pass) {
        __syncthreads();
        atomicAdd(&g_histc[b * CC + tid], shc[tid]);
        for (int i = tid; i < CC * BITS; i += 256)
            atomicAdd(&g_histb[b * CC * BITS + i], shb[i]);
    }
}

// ---------------- centroid update (and hist re-zero) ----------------
__global__ void kmeans_update()
{
    const int b = blockIdx.x, c = threadIdx.x;
    const int cnt = g_histc[b * CC + c];
    const unsigned old = g_cent[b * CC + c];
    unsigned nw = 0;
#pragma unroll
    for (int bit = 0; bit < BITS; bit++) {
        int s = g_histb[(b * CC + c) * BITS + bit];
        if (2 * s >= cnt) nw |= (1u << bit);
    }
    g_cent[b * CC + c] = (cnt > 0) ? nw : old;
    g_histc[b * CC + c] = 0;
#pragma unroll
    for (int bit = 0; bit < BITS; bit++) g_histb[(b * CC + c) * BITS + bit] = 0;
}

// ---------------- qc = segmented mean of q per cluster (deterministic via int64 fixed-point) ----------------
__global__ void __launch_bounds__(256) qc_kernel()
{
    __shared__ long long sq[CC * 17];     // 16 e-dims per block, pad 17
    const int b = blockIdx.y;
    const int eq = blockIdx.x * 16;
    const int tid = threadIdx.x;
    for (int i = tid; i < CC * 17; i += 256) sq[i] = 0;
    __syncthreads();
    for (int p = tid; p < LL; p += 256) {
        const int c = g_assign[b * LL + p];
        const float* q = &g_q[((size_t)(b * LL + p)) * 64 + eq];
#pragma unroll
        for (int e = 0; e < 16; e++) {
            long long v = (long long)llrintf(q[e] * 1073741824.0f);
            atomicAdd((unsigned long long*)&sq[c * 17 + e], (unsigned long long)v);
        }
    }
    __syncthreads();
    for (int i = tid; i < CC * 16; i += 256) {
        const int c = i / 16, e = i % 16;
        const float cnt = fmaxf((float)g_cnt[b * CC + c], 1.f);
        const double s = (double)sq[c * 17 + e] * (1.0 / 1073741824.0);
        g_qc[((size_t)(b * CC + c)) * 64 + eq + e] = (float)(s / (double)cnt);
    }
}

// ---------------- scores = TEMP * qc @ k^T  (per b: [256x64] x [64x4096]) ----------------
__global__ void __launch_bounds__(256) scores_kernel()
{
    // grid (32 s-tiles, 8 c-tiles, 64 b); tile = 32c x 128s, K=64 full
    __shared__ float qs[64][36];    // [e][c]
    __shared__ float ks[64][132];   // [e][s]
    const int b = blockIdx.z;
    const int c0 = blockIdx.y * 32;
    const int s0 = blockIdx.x * 128;
    const int tid = threadIdx.x;
    for (int i = tid; i < 32 * 16; i += 256) {
        int c = i / 16, e4 = (i % 16) * 4;
        float4 v = *(const float4*)&g_qc[((size_t)(b * CC + c0 + c)) * 64 + e4];
        qs[e4 + 0][c] = v.x; qs[e4 + 1][c] = v.y; qs[e4 + 2][c] = v.z; qs[e4 + 3][c] = v.w;
    }
    for (int i = tid; i < 128 * 16; i += 256) {
        int s = i / 16, e4 = (i % 16) * 4;
        float4 v = *(const float4*)&g_k[((size_t)(b * LL + s0 + s)) * 64 + e4];
        ks[e4 + 0][s] = v.x; ks[e4 + 1][s] = v.y; ks[e4 + 2][s] = v.z; ks[e4 + 3][s] = v.w;
    }
    __syncthreads();
    const int tx = tid % 16, ty = tid / 16;   // tx -> 8 s, ty -> 2 c
    float acc[2][8];
#pragma unroll
    for (int i = 0; i < 2; i++)
#pragma unroll
        for (int j = 0; j < 8; j++) acc[i][j] = 0.f;
#pragma unroll
    for (int e = 0; e < 64; e++) {
        float a[2], bv[8];
#pragma unroll
        for (int i = 0; i < 2; i++) a[i] = qs[e][ty * 2 + i];
#pragma unroll
        for (int j = 0; j < 8; j++) bv[j] = ks[e][tx * 8 + j];
#pragma unroll
        for (int i = 0; i < 2; i++)
#pragma unroll
            for (int j = 0; j < 8; j++)
                acc[i][j] = fmaf(a[i], bv[j], acc[i][j]);
    }
#pragma unroll
    for (int i = 0; i < 2; i++)
#pragma unroll
        for (int j = 0; j < 8; j++)
            g_scores[((size_t)(b * CC + c0 + ty * 2 + i)) * LL + s0 + tx * 8 + j] = acc[i][j] * TEMP_F;
}

// ---------------- row softmax over L=4096 ----------------
__global__ void __launch_bounds__(256) softmax_kernel()
{
    __shared__ float red[256];
    const size_t row = blockIdx.x;
    float4* p4 = (float4*)&g_scores[row * LL];
    const int tid = threadIdx.x;
    float4 v[4];
    float mx = -INFINITY;
#pragma unroll
    for (int i = 0; i < 4; i++) {
        v[i] = p4[tid + i * 256];
        mx = fmaxf(mx, fmaxf(fmaxf(v[i].x, v[i].y), fmaxf(v[i].z, v[i].w)));
    }
    red[tid] = mx; __syncthreads();
    for (int s = 128; s > 0; s >>= 1) { if (tid < s) red[tid] = fmaxf(red[tid], red[tid + s]); __syncthreads(); }
    mx = red[0]; __syncthreads();
    float sum = 0.f;
#pragma unroll
    for (int i = 0; i < 4; i++) {
        v[i].x = expf(v[i].x - mx); v[i].y = expf(v[i].y - mx);
        v[i].z = expf(v[i].z - mx); v[i].w = expf(v[i].w - mx);
        sum += (v[i].x + v[i].y) + (v[i].z + v[i].w);
    }
    red[tid] = sum; __syncthreads();
    for (int s = 128; s > 0; s >>= 1) { if (tid < s) red[tid] += red[tid + s]; __syncthreads(); }
    const float inv = 1.f / red[0];
#pragma unroll
    for (int i = 0; i < 4; i++) {
        v[i].x *= inv; v[i].y *= inv; v[i].z *= inv; v[i].w *= inv;
        p4[tid + i * 256] = v[i];
    }
}

// ---------------- vc = attn @ v  (per b: [256x4096] x [4096x64]) ----------------
__global__ void __launch_bounds__(256) vc_kernel()
{
    // grid (4 c-tiles, 64 b); tile 64c x 64e, K tiles of 32
    __shared__ float as_[32][68];   // [k][c]
    __shared__ float bs[32][64];    // [k][e]
    const int b = blockIdx.y;
    const int c0 = blockIdx.x * 64;
    const int tid = threadIdx.x;
    const int tx = tid % 16, ty = tid / 16;
    float acc[4][4];
#pragma unroll
    for (int i = 0; i < 4; i++)
#pragma unroll
        for (int j = 0; j < 4; j++) acc[i][j] = 0.f;

    for (int k0 = 0; k0 < LL; k0 += 32) {
        for (int i = tid; i < 64 * 8; i += 256) {
            int c = i / 8, k4 = (i % 8) * 4;
            float4 v = *(const float4*)&g_scores[((size_t)(b * CC + c0 + c)) * LL + k0 + k4];
            as_[k4 + 0][c] = v.x; as_[k4 + 1][c] = v.y; as_[k4 + 2][c] = v.z; as_[k4 + 3][c] = v.w;
        }
        for (int i = tid; i < 32 * 16; i += 256) {
            int k = i / 16, e4 = (i % 16) * 4;
            *(float4*)&bs[k][e4] = *(const float4*)&g_v[((size_t)(b * LL + k0 + k)) * 64 + e4];
        }
        __syncthreads();
#pragma unroll
        for (int k = 0; k < 32; k++) {
            float a[4], bv[4];
#pragma unroll
            for (int i = 0; i < 4; i++) a[i] = as_[k][ty * 4 + i];
#pragma unroll
            for (int j = 0; j < 4; j++) bv[j] = bs[k][tx * 4 + j];
#pragma unroll
            for (int i = 0; i < 4; i++)
#pragma unroll
                for (int j = 0; j < 4; j++)
                    acc[i][j] = fmaf(a[i], bv[j], acc[i][j]);
        }
        __syncthreads();
    }
#pragma unroll
    for (int i = 0; i < 4; i++)
#pragma unroll
        for (int j = 0; j < 4; j++)
            g_vc[((size_t)(b * CC + c0 + ty * 4 + i)) * 64 + tx * 4 + j] = acc[i][j];
}

// ---------------- gather: g_gat[n*L+l][h*64+e] = vc[b][assign[b][l]][e] ----------------
__global__ void __launch_bounds__(256) gather_kernel()
{
    const int t = blockIdx.x * 256 + threadIdx.x;   // 16384*256 threads
    const int m = t >> 8;
    const int rem = t & 255;
    const int h = rem >> 4, f = rem & 15;
    const int n = m >> 12, l = m & 4095;
    const int b = n * 16 + h;
    const int c = g_assign[b * LL + l];
    float4 v = *(const float4*)&g_vc[((size_t)(b * CC + c)) * 64 + f * 4];
    *(float4*)&g_gat[(size_t)m * 1024 + h * 64 + f * 4] = v;
}

// ---------------- launch ----------------
extern "C" void kernel_launch(void* const* d_in, const int* in_sizes, int n_in,
                              void* d_out, int out_size)
{
    const float* x      = (const float*)d_in[0];
    // d_in[1] = attention_mask (all ones, unused by reference math)
    const float* Wq     = (const float*)d_in[2];
    const float* bq     = (const float*)d_in[3];
    const float* Wk     = (const float*)d_in[4];
    const float* bk     = (const float*)d_in[5];
    const float* Wv     = (const float*)d_in[6];
    const float* bv     = (const float*)d_in[7];
    const float* Wo     = (const float*)d_in[8];
    const float* bo     = (const float*)d_in[9];
    const float* planes = (const float*)d_in[10];
    float* out = (float*)d_out;

    gemm_qkv<<<dim3(8, 256, 3), 256>>>(x, Wq, Wk, Wv, bq, bk, bv);
    codes_kernel<<<2048, 256>>>(planes);
    init_cent<<<64, 256>>>();
    for (int it = 0; it < KM_ITERS; it++) {
        kmeans_assign<<<dim3(4, 64), 256>>>(0);
        kmeans_update<<<64, 256>>>();
    }
    kmeans_assign<<<dim3(4, 64), 256>>>(1);
    qc_kernel<<<dim3(4, 64), 256>>>();
    scores_kernel<<<dim3(32, 8, 64), 256>>>();
    softmax_kernel<<<16384, 256>>>();
    vc_kernel<<<dim3(4, 64), 256>>>();
    gather_kernel<<<16384, 256>>>();
    gemm_out<<<dim3(8, 256), 256>>>(Wo, bo, out);
}

// round 8
// speedup vs baseline: 1.0138x; 1.0138x over previous
#include <cuda_runtime.h>
#include <cuda_bf16.h>
#include <math.h>
#include <limits.h>

// Problem constants
#define NB    4
#define LL    4096
#define DD    1024
#define HH    16
#define EE    64
#define BB    64          // NB*HH
#define CC    256
#define BITS  32
#define KM_ITERS 10
#define MM    16384       // NB*LL
#define TEMP_F 0.125f
#define KC    248         // Eigen mt-heuristic: l1=16K default, mr=12, nr=4 -> 248

// ---------------- scratch (__device__ globals; no allocation allowed) ----------------
__device__ float    g_q[(size_t)BB * LL * EE];
__device__ float    g_k[(size_t)BB * LL * EE];
__device__ float    g_v[(size_t)BB * LL * EE];
__device__ unsigned g_codes[BB * LL];
__device__ unsigned g_cent[BB * CC];
__device__ int      g_histc[BB * CC];
__device__ int      g_histb[BB * CC * BITS];
__device__ int      g_assign[BB * LL];
__device__ int      g_cnt[BB * CC];
__device__ float    g_qc[(size_t)BB * CC * EE];
__device__ float    g_vc[(size_t)BB * CC * EE];
__device__ float    g_gat[(size_t)MM * DD];

// =============== EXACT q GEMM (FROZEN — Eigen gebp emulation, KC=248 panels) ===============
// q = x @ Wq + bq with per-element arithmetic: five ascending-k FMA panels
// (248,248,248,248,32) folded sequentially with one f32 add each.
__global__ void __launch_bounds__(256) gemm_q(const float* __restrict__ A,
                                              const float* __restrict__ W,
                                              const float* __restrict__ bias)
{
    const int K = 1024, N = 1024;
    const int Mrow = blockIdx.y * 64;
    const int Ncol = blockIdx.x * 128;
    __shared__ float As[8][68];
    __shared__ float Ws[8][132];
    const int tid = threadIdx.x;
    const int tx = tid % 16, ty = tid / 16;
    const int arow = tid / 4;
    const int acol = (tid % 4) * 2;
    const int wrow = tid / 32;
    const int wcol = (tid % 32) * 4;

    float c_[4][8], t_[4][8];
#pragma unroll
    for (int i = 0; i < 4; i++)
#pragma unroll
        for (int j = 0; j < 8; j++) { c_[i][j] = 0.f; t_[i][j] = 0.f; }

    for (int kt = 0; kt < K; kt += 8) {
        {
            float2 av = *(const float2*)&A[(size_t)(Mrow + arow) * K + kt + acol];
            As[acol + 0][arow] = av.x;
            As[acol + 1][arow] = av.y;
        }
        {
            float4 wv = *(const float4*)&W[(size_t)(kt + wrow) * N + Ncol + wcol];
            *(float4*)&Ws[wrow][wcol] = wv;
        }
        __syncthreads();
#pragma unroll
        for (int kk = 0; kk < 8; kk++) {
            float a[4], b[8];
#pragma unroll
            for (int i = 0; i < 4; i++) a[i] = As[kk][ty * 4 + i];
#pragma unroll
            for (int j = 0; j < 8; j++) b[j] = Ws[kk][tx * 8 + j];
#pragma unroll
            for (int i = 0; i < 4; i++)
#pragma unroll
                for (int j = 0; j < 8; j++)
                    t_[i][j] = fmaf(a[i], b[j], t_[i][j]);
        }
        __syncthreads();
        const int kend = kt + 8;
        if ((kend % KC) == 0 || kend == K) {
#pragma unroll
            for (int i = 0; i < 4; i++)
#pragma unroll
                for (int j = 0; j < 8; j++) {
                    c_[i][j] = __fadd_rn(c_[i][j], t_[i][j]);
                    t_[i][j] = 0.f;
                }
        }
    }
#pragma unroll
    for (int i = 0; i < 4; i++) {
        int m = Mrow + ty * 4 + i;
#pragma unroll
        for (int j = 0; j < 8; j++) {
            int col = Ncol + tx * 8 + j;
            float val = c_[i][j] + bias[col];
            int n = m >> 12, l = m & 4095, h = col >> 6, e = col & 63;
            g_q[(((size_t)(n * 16 + h)) * 4096 + l) * 64 + e] = val;
        }
    }
}

// =============== FAST fp32 GEMM (continuous paths: k, v, out) ===============
// 128x128 tile, k-step 16, 8x8 per thread. Ordering is free here.
template<int MODE>
__device__ __forceinline__ void fast_gemm_body(const float* __restrict__ A,
                                               const float* __restrict__ W,
                                               const float* __restrict__ bias,
                                               float* __restrict__ out)
{
    const int K = 1024, N = 1024;
    const int Mrow = blockIdx.y * 128;
    const int Ncol = blockIdx.x * 128;
    __shared__ float As[16][132];
    __shared__ float Ws[16][132];
    const int tid = threadIdx.x;
    const int tx = tid % 16, ty = tid / 16;
    const int arow = tid / 4;
    const int acol = (tid % 4) * 4;
    const int wrow = tid / 32;
    const int wcol = (tid % 32) * 4;

    float acc[8][8];
#pragma unroll
    for (int i = 0; i < 8; i++)
#pragma unroll
        for (int j = 0; j < 8; j++) acc[i][j] = 0.f;

    for (int kt = 0; kt < K; kt += 16) {
#pragma unroll
        for (int i = 0; i < 2; i++) {
            float4 av = *(const float4*)&A[(size_t)(Mrow + arow + i * 64) * K + kt + acol];
            As[acol + 0][arow + i * 64] = av.x;
            As[acol + 1][arow + i * 64] = av.y;
            As[acol + 2][arow + i * 64] = av.z;
            As[acol + 3][arow + i * 64] = av.w;
        }
#pragma unroll
        for (int i = 0; i < 2; i++) {
            float4 wv = *(const float4*)&W[(size_t)(kt + wrow + i * 8) * N + Ncol + wcol];
            *(float4*)&Ws[wrow + i * 8][wcol] = wv;
        }
        __syncthreads();
#pragma unroll
        for (int kk = 0; kk < 16; kk++) {
            float a[8], b[8];
#pragma unroll
            for (int i = 0; i < 8; i++) a[i] = As[kk][ty * 8 + i];
#pragma unroll
            for (int j = 0; j < 8; j++) b[j] = Ws[kk][tx * 8 + j];
#pragma unroll
            for (int i = 0; i < 8; i++)
#pragma unroll
                for (int j = 0; j < 8; j++)
                    acc[i][j] = fmaf(a[i], b[j], acc[i][j]);
        }
        __syncthreads();
    }
#pragma unroll
    for (int i = 0; i < 8; i++) {
        int m = Mrow + ty * 8 + i;
#pragma unroll
        for (int j = 0; j < 8; j++) {
            int col = Ncol + tx * 8 + j;
            float val = acc[i][j] + bias[col];
            if (MODE == 1) {
                int n = m >> 12, l = m & 4095, h = col >> 6, e = col & 63;
                out[(((size_t)(n * 16 + h)) * 4096 + l) * 64 + e] = val;
            } else {
                out[(size_t)m * 1024 + col] = val;
            }
        }
    }
}

__global__ void __launch_bounds__(256) gemm_kv(const float* __restrict__ A,
                                               const float* __restrict__ Wk,
                                               const float* __restrict__ Wv,
                                               const float* __restrict__ bk,
                                               const float* __restrict__ bv)
{
    if (blockIdx.z == 0) fast_gemm_body<1>(A, Wk, bk, g_k);
    else                 fast_gemm_body<1>(A, Wv, bv, g_v);
}

__global__ void __launch_bounds__(256) gemm_out(const float* __restrict__ W,
                                                const float* __restrict__ bias,
                                                float* __restrict__ out)
{
    fast_gemm_body<0>(g_gat, W, bias, out);
}

// ---------------- codes = pack(q @ planes > 0)  (FROZEN) ----------------
__global__ void __launch_bounds__(256) codes_kernel(const float* __restrict__ planes)
{
    __shared__ float pl[64 * 32];
    const int tid = threadIdx.x;
    for (int i = tid; i < 2048; i += 256) pl[i] = planes[i];
    __syncthreads();
    const int warp = tid / 32, lane = tid % 32;
    const int rowBase = (blockIdx.x * 8 + warp) * 16;
    for (int r = 0; r < 16; r++) {
        const int row = rowBase + r;
        const float* qrow = &g_q[(size_t)row * 64];
        float s = 0.f;
#pragma unroll
        for (int e = 0; e < 64; e++)
            s = fmaf(__ldg(&qrow[e]), pl[e * 32 + lane], s);
        unsigned w = __ballot_sync(0xffffffffu, s > 0.f);
        if (lane == 0) g_codes[row] = w;
    }
}

// ---------------- centroid init (FROZEN) ----------------
__global__ void init_cent()
{
    const int b = blockIdx.x, c = threadIdx.x;
    int idx = (273 * c) / 17;
    g_cent[b * CC + c] = g_codes[b * LL + idx];
    g_histc[b * CC + c] = 0;
    g_cnt[b * CC + c] = 0;
#pragma unroll
    for (int bit = 0; bit < BITS; bit++) g_histb[(b * CC + c) * BITS + bit] = 0;
}

// ---------------- k-means assignment (FROZEN) ----------------
__global__ void __launch_bounds__(256) kmeans_assign(int final_pass)
{
    __shared__ unsigned scent[CC];
    __shared__ int shc[CC];
    __shared__ int shb[CC * BITS];
    const int b = blockIdx.y;
    const int tid = threadIdx.x;
    scent[tid] = g_cent[b * CC + tid];
    if (!final_pass) {
        shc[tid] = 0;
        for (int i = tid; i < CC * BITS; i += 256) shb[i] = 0;
    }
    __syncthreads();
    const int p0 = blockIdx.x * 1024;
    for (int p = p0 + tid; p < p0 + 1024; p += 256) {
        const unsigned w = g_codes[b * LL + p];
        int best = INT_MAX;
#pragma unroll 16
        for (int c = 0; c < CC; c++) {
            int d = __popc(w ^ scent[c]);
            best = min(best, (d << 8) | c);
        }
        const int bc = best & 255;
        if (final_pass) {
            g_assign[b * LL + p] = bc;
            atomicAdd(&g_cnt[b * CC + bc], 1);
        } else {
            atomicAdd(&shc[bc], 1);
            unsigned ww = w;
            while (ww) {
                int bit = __ffs(ww) - 1;
                ww &= ww - 1;
                atomicAdd(&shb[bc * BITS + bit], 1);
            }
        }
    }
    if (!final_pass) {
        __syncthreads();
        atomicAdd(&g_histc[b * CC + tid], shc[tid]);
        for (int i = tid; i < CC * BITS; i += 256)
            atomicAdd(&g_histb[b * CC * BITS + i], shb[i]);
    }
}

// ---------------- centroid update (FROZEN) ----------------
__global__ void kmeans_update()
{
    const int b = blockIdx.x, c = threadIdx.x;
    const int cnt = g_histc[b * CC + c];
    const unsigned old = g_cent[b * CC + c];
    unsigned nw = 0;
#pragma unroll
    for (int bit = 0; bit < BITS; bit++) {
        int s = g_histb[(b * CC + c) * BITS + bit];
        if (2 * s >= cnt) nw |= (1u << bit);
    }
    g_cent[b * CC + c] = (cnt > 0) ? nw : old;
    g_histc[b * CC + c] = 0;
#pragma unroll
    for (int bit = 0; bit < BITS; bit++) g_histb[(b * CC + c) * BITS + bit] = 0;
}

// ---------------- qc = segmented mean of q per cluster (FROZEN) ----------------
__global__ void __launch_bounds__(256) qc_kernel()
{
    __shared__ long long sq[CC * 17];
    const int b = blockIdx.y;
    const int eq = blockIdx.x * 16;
    const int tid = threadIdx.x;
    for (int i = tid; i < CC * 17; i += 256) sq[i] = 0;
    __syncthreads();
    for (int p = tid; p < LL; p += 256) {
        const int c = g_assign[b * LL + p];
        const float* q = &g_q[((size_t)(b * LL + p)) * 64 + eq];
#pragma unroll
        for (int e = 0; e < 16; e++) {
            long long v = (long long)llrintf(q[e] * 1073741824.0f);
            atomicAdd((unsigned long long*)&sq[c * 17 + e], (unsigned long long)v);
        }
    }
    __syncthreads();
    for (int i = tid; i < CC * 16; i += 256) {
        const int c = i / 16, e = i % 16;
        const float cnt = fmaxf((float)g_cnt[b * CC + c], 1.f);
        const double s = (double)sq[c * 17 + e] * (1.0 / 1073741824.0);
        g_qc[((size_t)(b * CC + c)) * 64 + eq + e] = (float)(s / (double)cnt);
    }
}

// ---------------- fused attention: vc = softmax(TEMP * qc@k^T) @ v ----------------
// One block per (b, 32-c tile). Scores are bounded (|s| small) -> unnormalized
// exp, single pass, deterministic fixed-order row sums, divide at the end.
__global__ void __launch_bounds__(256) attn_kernel()
{
    __shared__ float qcs[64][36];   // [e][c]
    __shared__ float kvs[64][68];   // k phase: [e][s]; v phase: [s][e]
    __shared__ float ps[32][68];    // exp(scores) [c][s]
    __shared__ float lsum[32];
    const int b = blockIdx.y;
    const int c0 = blockIdx.x * 32;
    const int tid = threadIdx.x;

    for (int i = tid; i < 32 * 16; i += 256) {
        int c = i / 16, e4 = (i % 16) * 4;
        float4 v = *(const float4*)&g_qc[((size_t)(b * CC + c0 + c)) * 64 + e4];
        qcs[e4 + 0][c] = v.x; qcs[e4 + 1][c] = v.y;
        qcs[e4 + 2][c] = v.z; qcs[e4 + 3][c] = v.w;
    }
    if (tid < 32) lsum[tid] = 0.f;

    const int cc = tid / 8;          // output c (0..31)
    const int eb = (tid % 8) * 8;    // output e base
    float acc[8];
#pragma unroll
    for (int j = 0; j < 8; j++) acc[j] = 0.f;
    __syncthreads();

    for (int s0 = 0; s0 < LL; s0 += 64) {
        // k tile transposed: kvs[e][s]
        for (int i = tid; i < 64 * 16; i += 256) {
            int s = i / 16, e4 = (i % 16) * 4;
            float4 v = *(const float4*)&g_k[((size_t)(b * LL + s0 + s)) * 64 + e4];
            kvs[e4 + 0][s] = v.x; kvs[e4 + 1][s] = v.y;
            kvs[e4 + 2][s] = v.z; kvs[e4 + 3][s] = v.w;
        }
        __syncthreads();
        // scores -> exp -> ps  (thread: 1 c x 8 s)
        {
            const int c = tid / 8;
            const int sb = (tid % 8) * 8;
            float sc[8];
#pragma unroll
            for (int j = 0; j < 8; j++) sc[j] = 0.f;
            for (int e = 0; e < 64; e++) {
                float a = qcs[e][c];
#pragma unroll
                for (int j = 0; j < 8; j++)
                    sc[j] = fmaf(a, kvs[e][sb + j], sc[j]);
            }
#pragma unroll
            for (int j = 0; j < 8; j++)
                ps[c][sb + j] = __expf(sc[j] * TEMP_F);
        }
        __syncthreads();
        // v tile (natural layout) + deterministic row sums
        for (int i = tid; i < 64 * 16; i += 256) {
            int s = i / 16, e4 = (i % 16) * 4;
            *(float4*)&kvs[s][e4] = *(const float4*)&g_v[((size_t)(b * LL + s0 + s)) * 64 + e4];
        }
        if (tid < 32) {
            float l = 0.f;
            for (int s = 0; s < 64; s++) l += ps[tid][s];
            lsum[tid] += l;
        }
        __syncthreads();
        // vc accumulate (thread: 1 c x 8 e)
        for (int s = 0; s < 64; s++) {
            float p = ps[cc][s];
#pragma unroll
            for (int j = 0; j < 8; j++)
                acc[j] = fmaf(p, kvs[s][eb + j], acc[j]);
        }
        __syncthreads();
    }
    const float inv = 1.f / lsum[cc];
#pragma unroll
    for (int j = 0; j < 8; j++)
        g_vc[((size_t)(b * CC + c0 + cc)) * 64 + eb + j] = acc[j] * inv;
}

// ---------------- gather: g_gat[n*L+l][h*64+e] = vc[b][assign[b][l]][e] ----------------
__global__ void __launch_bounds__(256) gather_kernel()
{
    const int t = blockIdx.x * 256 + threadIdx.x;
    const int m = t >> 8;
    const int rem = t & 255;
    const int h = rem >> 4, f = rem & 15;
    const int n = m >> 12, l = m & 4095;
    const int b = n * 16 + h;
    const int c = g_assign[b * LL + l];
    float4 v = *(const float4*)&g_vc[((size_t)(b * CC + c)) * 64 + f * 4];
    *(float4*)&g_gat[(size_t)m * 1024 + h * 64 + f * 4] = v;
}

// ---------------- launch ----------------
extern "C" void kernel_launch(void* const* d_in, const int* in_sizes, int n_in,
                              void* d_out, int out_size)
{
    const float* x      = (const float*)d_in[0];
    // d_in[1] = attention_mask (all ones, unused by reference math)
    const float* Wq     = (const float*)d_in[2];
    const float* bq     = (const float*)d_in[3];
    const float* Wk     = (const float*)d_in[4];
    const float* bk     = (const float*)d_in[5];
    const float* Wv     = (const float*)d_in[6];
    const float* bv     = (const float*)d_in[7];
    const float* Wo     = (const float*)d_in[8];
    const float* bo     = (const float*)d_in[9];
    const float* planes = (const float*)d_in[10];
    float* out = (float*)d_out;

    gemm_q<<<dim3(8, 256), 256>>>(x, Wq, bq);                 // EXACT (frozen)
    gemm_kv<<<dim3(8, 128, 2), 256>>>(x, Wk, Wv, bk, bv);     // fast
    codes_kernel<<<2048, 256>>>(planes);
    init_cent<<<64, 256>>>();
    for (int it = 0; it < KM_ITERS; it++) {
        kmeans_assign<<<dim3(4, 64), 256>>>(0);
        kmeans_update<<<64, 256>>>();
    }
    kmeans_assign<<<dim3(4, 64), 256>>>(1);
    qc_kernel<<<dim3(4, 64), 256>>>();
    attn_kernel<<<dim3(8, 64), 256>>>();                      // fused scores+softmax+vc
    gather_kernel<<<16384, 256>>>();
    gemm_out<<<dim3(8, 128), 256>>>(Wo, bo, out);             // fast
}

// round 9
// speedup vs baseline: 1.2473x; 1.2303x over previous
#include <cuda_runtime.h>
#include <cuda_bf16.h>
#include <math.h>
#include <limits.h>

// Problem constants
#define NB    4
#define LL    4096
#define DD    1024
#define HH    16
#define EE    64
#define BB    64          // NB*HH
#define CC    256
#define BITS  32
#define KM_ITERS 10
#define MM    16384       // NB*LL
#define TEMP_F 0.125f
#define KC    248         // Eigen mt-heuristic: l1=16K default, mr=12, nr=4 -> 248

// ---------------- scratch (__device__ globals; no allocation allowed) ----------------
__device__ float    g_q[(size_t)BB * LL * EE];
__device__ float    g_k[(size_t)BB * LL * EE];
__device__ float    g_v[(size_t)BB * LL * EE];
__device__ unsigned g_codes[BB * LL];
__device__ int      g_assign[BB * LL];
__device__ int      g_cnt[BB * CC];
__device__ float    g_qc[(size_t)BB * CC * EE];
__device__ float    g_vc[(size_t)BB * CC * EE];

// =============== EXACT q GEMM (FROZEN — Eigen gebp emulation, KC=248 panels) ===============
__global__ void __launch_bounds__(256) gemm_q(const float* __restrict__ A,
                                              const float* __restrict__ W,
                                              const float* __restrict__ bias)
{
    const int K = 1024, N = 1024;
    const int Mrow = blockIdx.y * 64;
    const int Ncol = blockIdx.x * 128;
    __shared__ float As[8][68];
    __shared__ float Ws[8][132];
    const int tid = threadIdx.x;
    const int tx = tid % 16, ty = tid / 16;
    const int arow = tid / 4;
    const int acol = (tid % 4) * 2;
    const int wrow = tid / 32;
    const int wcol = (tid % 32) * 4;

    float c_[4][8], t_[4][8];
#pragma unroll
    for (int i = 0; i < 4; i++)
#pragma unroll
        for (int j = 0; j < 8; j++) { c_[i][j] = 0.f; t_[i][j] = 0.f; }

    for (int kt = 0; kt < K; kt += 8) {
        {
            float2 av = *(const float2*)&A[(size_t)(Mrow + arow) * K + kt + acol];
            As[acol + 0][arow] = av.x;
            As[acol + 1][arow] = av.y;
        }
        {
            float4 wv = *(const float4*)&W[(size_t)(kt + wrow) * N + Ncol + wcol];
            *(float4*)&Ws[wrow][wcol] = wv;
        }
        __syncthreads();
#pragma unroll
        for (int kk = 0; kk < 8; kk++) {
            float a[4], b[8];
#pragma unroll
            for (int i = 0; i < 4; i++) a[i] = As[kk][ty * 4 + i];
#pragma unroll
            for (int j = 0; j < 8; j++) b[j] = Ws[kk][tx * 8 + j];
#pragma unroll
            for (int i = 0; i < 4; i++)
#pragma unroll
                for (int j = 0; j < 8; j++)
                    t_[i][j] = fmaf(a[i], b[j], t_[i][j]);
        }
        __syncthreads();
        const int kend = kt + 8;
        if ((kend % KC) == 0 || kend == K) {
#pragma unroll
            for (int i = 0; i < 4; i++)
#pragma unroll
                for (int j = 0; j < 8; j++) {
                    c_[i][j] = __fadd_rn(c_[i][j], t_[i][j]);
                    t_[i][j] = 0.f;
                }
        }
    }
#pragma unroll
    for (int i = 0; i < 4; i++) {
        int m = Mrow + ty * 4 + i;
#pragma unroll
        for (int j = 0; j < 8; j++) {
            int col = Ncol + tx * 8 + j;
            float val = c_[i][j] + bias[col];
            int n = m >> 12, l = m & 4095, h = col >> 6, e = col & 63;
            g_q[(((size_t)(n * 16 + h)) * 4096 + l) * 64 + e] = val;
        }
    }
}

// =============== FAST fp32 GEMM for k, v (continuous paths) ===============
__device__ __forceinline__ void fast_gemm_kv_body(const float* __restrict__ A,
                                                  const float* __restrict__ W,
                                                  const float* __restrict__ bias,
                                                  float* __restrict__ out)
{
    const int K = 1024, N = 1024;
    const int Mrow = blockIdx.y * 128;
    const int Ncol = blockIdx.x * 128;
    __shared__ float As[16][132];
    __shared__ float Ws[16][132];
    const int tid = threadIdx.x;
    const int tx = tid % 16, ty = tid / 16;
    const int arow = tid / 4;
    const int acol = (tid % 4) * 4;
    const int wrow = tid / 32;
    const int wcol = (tid % 32) * 4;

    float acc[8][8];
#pragma unroll
    for (int i = 0; i < 8; i++)
#pragma unroll
        for (int j = 0; j < 8; j++) acc[i][j] = 0.f;

    for (int kt = 0; kt < K; kt += 16) {
#pragma unroll
        for (int i = 0; i < 2; i++) {
            float4 av = *(const float4*)&A[(size_t)(Mrow + arow + i * 64) * K + kt + acol];
            As[acol + 0][arow + i * 64] = av.x;
            As[acol + 1][arow + i * 64] = av.y;
            As[acol + 2][arow + i * 64] = av.z;
            As[acol + 3][arow + i * 64] = av.w;
        }
#pragma unroll
        for (int i = 0; i < 2; i++) {
            float4 wv = *(const float4*)&W[(size_t)(kt + wrow + i * 8) * N + Ncol + wcol];
            *(float4*)&Ws[wrow + i * 8][wcol] = wv;
        }
        __syncthreads();
#pragma unroll
        for (int kk = 0; kk < 16; kk++) {
            float a[8], b[8];
#pragma unroll
            for (int i = 0; i < 8; i++) a[i] = As[kk][ty * 8 + i];
#pragma unroll
            for (int j = 0; j < 8; j++) b[j] = Ws[kk][tx * 8 + j];
#pragma unroll
            for (int i = 0; i < 8; i++)
#pragma unroll
                for (int j = 0; j < 8; j++)
                    acc[i][j] = fmaf(a[i], b[j], acc[i][j]);
        }
        __syncthreads();
    }
#pragma unroll
    for (int i = 0; i < 8; i++) {
        int m = Mrow + ty * 8 + i;
#pragma unroll
        for (int j = 0; j < 8; j++) {
            int col = Ncol + tx * 8 + j;
            float val = acc[i][j] + bias[col];
            int n = m >> 12, l = m & 4095, h = col >> 6, e = col & 63;
            out[(((size_t)(n * 16 + h)) * 4096 + l) * 64 + e] = val;
        }
    }
}

__global__ void __launch_bounds__(256) gemm_kv(const float* __restrict__ A,
                                               const float* __restrict__ Wk,
                                               const float* __restrict__ Wv,
                                               const float* __restrict__ bk,
                                               const float* __restrict__ bv)
{
    if (blockIdx.z == 0) fast_gemm_kv_body(A, Wk, bk, g_k);
    else                 fast_gemm_kv_body(A, Wv, bv, g_v);
}

// =============== output GEMM with fused gather: out = gather(vc) @ Wo + bo ===============
// A[m][col] = g_vc[(b, assign[b][l])][e] with b = (m>>12)*16 + col>>6, e = col&63.
__global__ void __launch_bounds__(256) gemm_out_g(const float* __restrict__ W,
                                                  const float* __restrict__ bias,
                                                  float* __restrict__ out)
{
    const int K = 1024, N = 1024;
    const int Mrow = blockIdx.y * 128;
    const int Ncol = blockIdx.x * 128;
    __shared__ float As[16][132];
    __shared__ float Ws[16][132];
    const int tid = threadIdx.x;
    const int tx = tid % 16, ty = tid / 16;
    const int arow = tid / 4;
    const int acol = (tid % 4) * 4;
    const int wrow = tid / 32;
    const int wcol = (tid % 32) * 4;

    float acc[8][8];
#pragma unroll
    for (int i = 0; i < 8; i++)
#pragma unroll
        for (int j = 0; j < 8; j++) acc[i][j] = 0.f;

    for (int kt = 0; kt < K; kt += 16) {
#pragma unroll
        for (int i = 0; i < 2; i++) {
            const int m = Mrow + arow + i * 64;
            const int col = kt + acol;
            const int n = m >> 12, l = m & 4095;
            const int h = col >> 6, e4 = col & 63;
            const int b = n * 16 + h;
            const int c = g_assign[b * LL + l];
            float4 av = *(const float4*)&g_vc[((size_t)(b * CC + c)) * 64 + e4];
            As[acol + 0][arow + i * 64] = av.x;
            As[acol + 1][arow + i * 64] = av.y;
            As[acol + 2][arow + i * 64] = av.z;
            As[acol + 3][arow + i * 64] = av.w;
        }
#pragma unroll
        for (int i = 0; i < 2; i++) {
            float4 wv = *(const float4*)&W[(size_t)(kt + wrow + i * 8) * N + Ncol + wcol];
            *(float4*)&Ws[wrow + i * 8][wcol] = wv;
        }
        __syncthreads();
#pragma unroll
        for (int kk = 0; kk < 16; kk++) {
            float a[8], b[8];
#pragma unroll
            for (int i = 0; i < 8; i++) a[i] = As[kk][ty * 8 + i];
#pragma unroll
            for (int j = 0; j < 8; j++) b[j] = Ws[kk][tx * 8 + j];
#pragma unroll
            for (int i = 0; i < 8; i++)
#pragma unroll
                for (int j = 0; j < 8; j++)
                    acc[i][j] = fmaf(a[i], b[j], acc[i][j]);
        }
        __syncthreads();
    }
#pragma unroll
    for (int i = 0; i < 8; i++) {
        int m = Mrow + ty * 8 + i;
#pragma unroll
        for (int j = 0; j < 8; j++) {
            int col = Ncol + tx * 8 + j;
            out[(size_t)m * 1024 + col] = acc[i][j] + bias[col];
        }
    }
}

// ---------------- codes = pack(q @ planes > 0)  (FROZEN) ----------------
__global__ void __launch_bounds__(256) codes_kernel(const float* __restrict__ planes)
{
    __shared__ float pl[64 * 32];
    const int tid = threadIdx.x;
    for (int i = tid; i < 2048; i += 256) pl[i] = planes[i];
    __syncthreads();
    const int warp = tid / 32, lane = tid % 32;
    const int rowBase = (blockIdx.x * 8 + warp) * 16;
    for (int r = 0; r < 16; r++) {
        const int row = rowBase + r;
        const float* qrow = &g_q[(size_t)row * 64];
        float s = 0.f;
#pragma unroll
        for (int e = 0; e < 64; e++)
            s = fmaf(__ldg(&qrow[e]), pl[e * 32 + lane], s);
        unsigned w = __ballot_sync(0xffffffffu, s > 0.f);
        if (lane == 0) g_codes[row] = w;
    }
}

// ---------------- fully fused k-means: init + 10 iters + final assign (integer-exact) ----------------
// One block per b. codes resident in smem; histogram = packed dual 16-bit counters
// (max count 4096 < 2^16, no carry between halves). Arithmetic identical to the
// previous init_cent / kmeans_assign / kmeans_update chain.
__global__ void __launch_bounds__(256) kmeans_full()
{
    __shared__ unsigned scodes[LL];      // 16 KB
    __shared__ unsigned scent[CC];
    __shared__ unsigned shb[CC * 16];    // 16 KB packed bit-counters
    __shared__ int shc[CC];
    const int b = blockIdx.x;
    const int tid = threadIdx.x;
    for (int i = tid; i < LL; i += 256) scodes[i] = g_codes[b * LL + i];
    __syncthreads();
    // centroid init: EXACT floor of linspace(0, L-1, C) = (273*c)/17
    scent[tid] = scodes[(273 * tid) / 17];
    __syncthreads();

    for (int it = 0; it < KM_ITERS; it++) {
        shc[tid] = 0;
        for (int i = tid; i < CC * 16; i += 256) shb[i] = 0;
        __syncthreads();
        for (int p = tid; p < LL; p += 256) {
            const unsigned w = scodes[p];
            int best = INT_MAX;
#pragma unroll 16
            for (int c = 0; c < CC; c++) {
                int d = __popc(w ^ scent[c]);
                best = min(best, (d << 8) | c);
            }
            const int bc = best & 255;
            atomicAdd(&shc[bc], 1);
#pragma unroll
            for (int j = 0; j < 16; j++) {
                unsigned contrib = ((w >> (2 * j)) & 1u) | (((w >> (2 * j + 1)) & 1u) << 16);
                if (contrib) atomicAdd(&shb[bc * 16 + j], contrib);
            }
        }
        __syncthreads();
        {   // update (tid == c); cnt==0 keeps old centroid — same rule as before
            const int cnt = shc[tid];
            const unsigned old = scent[tid];
            unsigned nw = 0;
#pragma unroll
            for (int j = 0; j < 16; j++) {
                const unsigned pk = shb[tid * 16 + j];
                const int s0 = (int)(pk & 0xffffu);
                const int s1 = (int)(pk >> 16);
                if (2 * s0 >= cnt) nw |= 1u << (2 * j);
                if (2 * s1 >= cnt) nw |= 1u << (2 * j + 1);
            }
            __syncthreads();
            scent[tid] = (cnt > 0) ? nw : old;
        }
        __syncthreads();
    }
    // final assignment + counts
    shc[tid] = 0;
    __syncthreads();
    for (int p = tid; p < LL; p += 256) {
        const unsigned w = scodes[p];
        int best = INT_MAX;
#pragma unroll 16
        for (int c = 0; c < CC; c++) {
            int d = __popc(w ^ scent[c]);
            best = min(best, (d << 8) | c);
        }
        const int bc = best & 255;
        g_assign[b * LL + p] = bc;
        atomicAdd(&shc[bc], 1);
    }
    __syncthreads();
    g_cnt[b * CC + tid] = shc[tid];
}

// ---------------- qc = segmented mean of q per cluster (FROZEN) ----------------
__global__ void __launch_bounds__(256) qc_kernel()
{
    __shared__ long long sq[CC * 17];
    const int b = blockIdx.y;
    const int eq = blockIdx.x * 16;
    const int tid = threadIdx.x;
    for (int i = tid; i < CC * 17; i += 256) sq[i] = 0;
    __syncthreads();
    for (int p = tid; p < LL; p += 256) {
        const int c = g_assign[b * LL + p];
        const float* q = &g_q[((size_t)(b * LL + p)) * 64 + eq];
#pragma unroll
        for (int e = 0; e < 16; e++) {
            long long v = (long long)llrintf(q[e] * 1073741824.0f);
            atomicAdd((unsigned long long*)&sq[c * 17 + e], (unsigned long long)v);
        }
    }
    __syncthreads();
    for (int i = tid; i < CC * 16; i += 256) {
        const int c = i / 16, e = i % 16;
        const float cnt = fmaxf((float)g_cnt[b * CC + c], 1.f);
        const double s = (double)sq[c * 17 + e] * (1.0 / 1073741824.0);
        g_qc[((size_t)(b * CC + c)) * 64 + eq + e] = (float)(s / (double)cnt);
    }
}

// ---------------- fused attention: vc = softmax(TEMP * qc@k^T) @ v ----------------
// Block per (b, 32-c tile); 2c x 4s / 2c x 4e register tiling, float4 smem reads.
__global__ void __launch_bounds__(256) attn_kernel()
{
    __shared__ float qcs[64][36];   // [e][c]
    __shared__ float kvs[64][68];   // k phase: [e][s]; v phase: [s][e]
    __shared__ float ps[32][68];    // exp(scores) [c][s]
    __shared__ float lsum[32];
    const int b = blockIdx.y;
    const int c0 = blockIdx.x * 32;
    const int tid = threadIdx.x;
    const int sx = tid % 16;        // 4 s (or 4 e) each
    const int cy = tid / 16;        // 2 c each

    for (int i = tid; i < 32 * 16; i += 256) {
        int c = i / 16, e4 = (i % 16) * 4;
        float4 v = *(const float4*)&g_qc[((size_t)(b * CC + c0 + c)) * 64 + e4];
        qcs[e4 + 0][c] = v.x; qcs[e4 + 1][c] = v.y;
        qcs[e4 + 2][c] = v.z; qcs[e4 + 3][c] = v.w;
    }
    if (tid < 32) lsum[tid] = 0.f;

    float acc[2][4];
#pragma unroll
    for (int i = 0; i < 2; i++)
#pragma unroll
        for (int j = 0; j < 4; j++) acc[i][j] = 0.f;
    __syncthreads();

    for (int s0 = 0; s0 < LL; s0 += 64) {
        // k tile transposed: kvs[e][s]
        for (int i = tid; i < 64 * 16; i += 256) {
            int s = i / 16, e4 = (i % 16) * 4;
            float4 v = *(const float4*)&g_k[((size_t)(b * LL + s0 + s)) * 64 + e4];
            kvs[e4 + 0][s] = v.x; kvs[e4 + 1][s] = v.y;
            kvs[e4 + 2][s] = v.z; kvs[e4 + 3][s] = v.w;
        }
        __syncthreads();
        // scores -> exp -> ps  (thread: 2c x 4s)
        {
            float sc[2][4];
#pragma unroll
            for (int i = 0; i < 2; i++)
#pragma unroll
                for (int j = 0; j < 4; j++) sc[i][j] = 0.f;
            for (int e = 0; e < 64; e++) {
                float a0 = qcs[e][cy * 2 + 0];
                float a1 = qcs[e][cy * 2 + 1];
                float4 bb = *(const float4*)&kvs[e][sx * 4];
                sc[0][0] = fmaf(a0, bb.x, sc[0][0]); sc[0][1] = fmaf(a0, bb.y, sc[0][1]);
                sc[0][2] = fmaf(a0, bb.z, sc[0][2]); sc[0][3] = fmaf(a0, bb.w, sc[0][3]);
                sc[1][0] = fmaf(a1, bb.x, sc[1][0]); sc[1][1] = fmaf(a1, bb.y, sc[1][1]);
                sc[1][2] = fmaf(a1, bb.z, sc[1][2]); sc[1][3] = fmaf(a1, bb.w, sc[1][3]);
            }
#pragma unroll
            for (int i = 0; i < 2; i++)
#pragma unroll
                for (int j = 0; j < 4; j++)
                    ps[cy * 2 + i][sx * 4 + j] = __expf(sc[i][j] * TEMP_F);
        }
        __syncthreads();
        // v tile (natural layout [s][e]) + deterministic row sums
        for (int i = tid; i < 64 * 16; i += 256) {
            int s = i / 16, e4 = (i % 16) * 4;
            *(float4*)&kvs[s][e4] = *(const float4*)&g_v[((size_t)(b * LL + s0 + s)) * 64 + e4];
        }
        if (tid < 32) {
            float l = 0.f;
            for (int s = 0; s < 64; s++) l += ps[tid][s];
            lsum[tid] += l;
        }
        __syncthreads();
        // vc accumulate (thread: 2c x 4e)
        for (int s = 0; s < 64; s++) {
            float p0 = ps[cy * 2 + 0][s];
            float p1 = ps[cy * 2 + 1][s];
            float4 vv = *(const float4*)&kvs[s][sx * 4];
            acc[0][0] = fmaf(p0, vv.x, acc[0][0]); acc[0][1] = fmaf(p0, vv.y, acc[0][1]);
            acc[0][2] = fmaf(p0, vv.z, acc[0][2]); acc[0][3] = fmaf(p0, vv.w, acc[0][3]);
            acc[1][0] = fmaf(p1, vv.x, acc[1][0]); acc[1][1] = fmaf(p1, vv.y, acc[1][1]);
            acc[1][2] = fmaf(p1, vv.z, acc[1][2]); acc[1][3] = fmaf(p1, vv.w, acc[1][3]);
        }
        __syncthreads();
    }
#pragma unroll
    for (int i = 0; i < 2; i++) {
        const float inv = 1.f / lsum[cy * 2 + i];
#pragma unroll
        for (int j = 0; j < 4; j++)
            g_vc[((size_t)(b * CC + c0 + cy * 2 + i)) * 64 + sx * 4 + j] = acc[i][j] * inv;
    }
}

// ---------------- launch ----------------
extern "C" void kernel_launch(void* const* d_in, const int* in_sizes, int n_in,
                              void* d_out, int out_size)
{
    const float* x      = (const float*)d_in[0];
    // d_in[1] = attention_mask (all ones, unused by reference math)
    const float* Wq     = (const float*)d_in[2];
    const float* bq     = (const float*)d_in[3];
    const float* Wk     = (const float*)d_in[4];
    const float* bk     = (const float*)d_in[5];
    const float* Wv     = (const float*)d_in[6];
    const float* bv     = (const float*)d_in[7];
    const float* Wo     = (const float*)d_in[8];
    const float* bo     = (const float*)d_in[9];
    const float* planes = (const float*)d_in[10];
    float* out = (float*)d_out;

    gemm_q<<<dim3(8, 256), 256>>>(x, Wq, bq);                 // EXACT (frozen)
    gemm_kv<<<dim3(8, 128, 2), 256>>>(x, Wk, Wv, bk, bv);     // fast fp32
    codes_kernel<<<2048, 256>>>(planes);                      // FROZEN
    kmeans_full<<<64, 256>>>();                               // fused, integer-exact
    qc_kernel<<<dim3(4, 64), 256>>>();                        // FROZEN
    attn_kernel<<<dim3(8, 64), 256>>>();                      // fused attention
    gemm_out_g<<<dim3(8, 128), 256>>>(Wo, bo, out);           // out GEMM + fused gather
}

// round 10
// speedup vs baseline: 1.3342x; 1.0696x over previous
#include <cuda_runtime.h>
#include <cuda_bf16.h>
#include <math.h>
#include <limits.h>

// Problem constants
#define NB    4
#define LL    4096
#define DD    1024
#define HH    16
#define EE    64
#define BB    64          // NB*HH
#define CC    256
#define BITS  32
#define KM_ITERS 10
#define MM    16384       // NB*LL
#define TEMP_F 0.125f
#define KC    248         // Eigen mt-heuristic: l1=16K default, mr=12, nr=4 -> 248

// ---------------- scratch (__device__ globals; no allocation allowed) ----------------
__device__ float    g_q[(size_t)BB * LL * EE];
__device__ float    g_k[(size_t)BB * LL * EE];
__device__ float    g_v[(size_t)BB * LL * EE];
__device__ unsigned g_codes[BB * LL];
__device__ unsigned g_cent[BB * CC];
__device__ int      g_histc[BB * CC];
__device__ unsigned g_histb[BB * CC * 16];   // packed dual 16-bit bit-counters
__device__ int      g_assign[BB * LL];
__device__ int      g_cnt[BB * CC];
__device__ float    g_qc[(size_t)BB * CC * EE];
__device__ float    g_vc[(size_t)BB * CC * EE];

// =============== EXACT q GEMM (FROZEN ARITHMETIC — Eigen gebp, KC=248 panels) ===============
// Per-output sequence: ascending-k FMA chains, folds at k=248,496,744,992,1024.
// Staging k in 32s (folds checked per 8-group; all fold points are multiples of 8).
__global__ void __launch_bounds__(256) gemm_q(const float* __restrict__ A,
                                              const float* __restrict__ W,
                                              const float* __restrict__ bias)
{
    const int K = 1024, N = 1024;
    const int Mrow = blockIdx.y * 64;
    const int Ncol = blockIdx.x * 128;
    __shared__ float As[32][68];     // [k][row]
    __shared__ float Ws[32][132];    // [k][col]
    const int tid = threadIdx.x;
    const int tx = tid % 16, ty = tid / 16;
    const int arow = tid / 4;                 // 0..63
    const int acol = (tid % 4) * 8;           // 0,8,16,24
    const int wrow = tid / 32;                // 0..7
    const int wcol = (tid % 32) * 4;

    float c_[4][8], t_[4][8];
#pragma unroll
    for (int i = 0; i < 4; i++)
#pragma unroll
        for (int j = 0; j < 8; j++) { c_[i][j] = 0.f; t_[i][j] = 0.f; }

    for (int kt = 0; kt < K; kt += 32) {
        {
            const float* arow_p = &A[(size_t)(Mrow + arow) * K + kt + acol];
            float4 a0 = *(const float4*)&arow_p[0];
            float4 a1 = *(const float4*)&arow_p[4];
            As[acol + 0][arow] = a0.x; As[acol + 1][arow] = a0.y;
            As[acol + 2][arow] = a0.z; As[acol + 3][arow] = a0.w;
            As[acol + 4][arow] = a1.x; As[acol + 5][arow] = a1.y;
            As[acol + 6][arow] = a1.z; As[acol + 7][arow] = a1.w;
        }
#pragma unroll
        for (int r = 0; r < 4; r++) {
            float4 wv = *(const float4*)&W[(size_t)(kt + wrow + r * 8) * N + Ncol + wcol];
            *(float4*)&Ws[wrow + r * 8][wcol] = wv;
        }
        __syncthreads();
#pragma unroll
        for (int g = 0; g < 4; g++) {
#pragma unroll
            for (int kk8 = 0; kk8 < 8; kk8++) {
                const int kk = g * 8 + kk8;
                float4 av = *(const float4*)&As[kk][ty * 4];
                float4 b0 = *(const float4*)&Ws[kk][tx * 8];
                float4 b1 = *(const float4*)&Ws[kk][tx * 8 + 4];
                float a[4] = {av.x, av.y, av.z, av.w};
                float b[8] = {b0.x, b0.y, b0.z, b0.w, b1.x, b1.y, b1.z, b1.w};
#pragma unroll
                for (int i = 0; i < 4; i++)
#pragma unroll
                    for (int j = 0; j < 8; j++)
                        t_[i][j] = fmaf(a[i], b[j], t_[i][j]);
            }
            const int kend = kt + g * 8 + 8;
            if (kend == 248 || kend == 496 || kend == 744 || kend == 992 || kend == 1024) {
#pragma unroll
                for (int i = 0; i < 4; i++)
#pragma unroll
                    for (int j = 0; j < 8; j++) {
                        c_[i][j] = __fadd_rn(c_[i][j], t_[i][j]);
                        t_[i][j] = 0.f;
                    }
            }
        }
        __syncthreads();
    }
#pragma unroll
    for (int i = 0; i < 4; i++) {
        int m = Mrow + ty * 4 + i;
#pragma unroll
        for (int j = 0; j < 8; j++) {
            int col = Ncol + tx * 8 + j;
            float val = c_[i][j] + bias[col];
            int n = m >> 12, l = m & 4095, h = col >> 6, e = col & 63;
            g_q[(((size_t)(n * 16 + h)) * 4096 + l) * 64 + e] = val;
        }
    }
}

// =============== FAST fp32 GEMM for k, v (continuous paths) ===============
__device__ __forceinline__ void fast_gemm_kv_body(const float* __restrict__ A,
                                                  const float* __restrict__ W,
                                                  const float* __restrict__ bias,
                                                  float* __restrict__ out)
{
    const int K = 1024, N = 1024;
    const int Mrow = blockIdx.y * 128;
    const int Ncol = blockIdx.x * 128;
    __shared__ float As[16][132];
    __shared__ float Ws[16][132];
    const int tid = threadIdx.x;
    const int tx = tid % 16, ty = tid / 16;
    const int arow = tid / 4;
    const int acol = (tid % 4) * 4;
    const int wrow = tid / 32;
    const int wcol = (tid % 32) * 4;

    float acc[8][8];
#pragma unroll
    for (int i = 0; i < 8; i++)
#pragma unroll
        for (int j = 0; j < 8; j++) acc[i][j] = 0.f;

    for (int kt = 0; kt < K; kt += 16) {
#pragma unroll
        for (int i = 0; i < 2; i++) {
            float4 av = *(const float4*)&A[(size_t)(Mrow + arow + i * 64) * K + kt + acol];
            As[acol + 0][arow + i * 64] = av.x;
            As[acol + 1][arow + i * 64] = av.y;
            As[acol + 2][arow + i * 64] = av.z;
            As[acol + 3][arow + i * 64] = av.w;
        }
#pragma unroll
        for (int i = 0; i < 2; i++) {
            float4 wv = *(const float4*)&W[(size_t)(kt + wrow + i * 8) * N + Ncol + wcol];
            *(float4*)&Ws[wrow + i * 8][wcol] = wv;
        }
        __syncthreads();
#pragma unroll
        for (int kk = 0; kk < 16; kk++) {
            float a[8], b[8];
#pragma unroll
            for (int i = 0; i < 8; i++) a[i] = As[kk][ty * 8 + i];
#pragma unroll
            for (int j = 0; j < 8; j++) b[j] = Ws[kk][tx * 8 + j];
#pragma unroll
            for (int i = 0; i < 8; i++)
#pragma unroll
                for (int j = 0; j < 8; j++)
                    acc[i][j] = fmaf(a[i], b[j], acc[i][j]);
        }
        __syncthreads();
    }
#pragma unroll
    for (int i = 0; i < 8; i++) {
        int m = Mrow + ty * 8 + i;
#pragma unroll
        for (int j = 0; j < 8; j++) {
            int col = Ncol + tx * 8 + j;
            float val = acc[i][j] + bias[col];
            int n = m >> 12, l = m & 4095, h = col >> 6, e = col & 63;
            out[(((size_t)(n * 16 + h)) * 4096 + l) * 64 + e] = val;
        }
    }
}

__global__ void __launch_bounds__(256) gemm_kv(const float* __restrict__ A,
                                               const float* __restrict__ Wk,
                                               const float* __restrict__ Wv,
                                               const float* __restrict__ bk,
                                               const float* __restrict__ bv)
{
    if (blockIdx.z == 0) fast_gemm_kv_body(A, Wk, bk, g_k);
    else                 fast_gemm_kv_body(A, Wv, bv, g_v);
}

// =============== output GEMM with fused gather: out = gather(vc) @ Wo + bo ===============
__global__ void __launch_bounds__(256) gemm_out_g(const float* __restrict__ W,
                                                  const float* __restrict__ bias,
                                                  float* __restrict__ out)
{
    const int K = 1024, N = 1024;
    const int Mrow = blockIdx.y * 128;
    const int Ncol = blockIdx.x * 128;
    __shared__ float As[16][132];
    __shared__ float Ws[16][132];
    const int tid = threadIdx.x;
    const int tx = tid % 16, ty = tid / 16;
    const int arow = tid / 4;
    const int acol = (tid % 4) * 4;
    const int wrow = tid / 32;
    const int wcol = (tid % 32) * 4;

    float acc[8][8];
#pragma unroll
    for (int i = 0; i < 8; i++)
#pragma unroll
        for (int j = 0; j < 8; j++) acc[i][j] = 0.f;

    for (int kt = 0; kt < K; kt += 16) {
#pragma unroll
        for (int i = 0; i < 2; i++) {
            const int m = Mrow + arow + i * 64;
            const int col = kt + acol;
            const int n = m >> 12, l = m & 4095;
            const int h = col >> 6, e4 = col & 63;
            const int b = n * 16 + h;
            const int c = g_assign[b * LL + l];
            float4 av = *(const float4*)&g_vc[((size_t)(b * CC + c)) * 64 + e4];
            As[acol + 0][arow + i * 64] = av.x;
            As[acol + 1][arow + i * 64] = av.y;
            As[acol + 2][arow + i * 64] = av.z;
            As[acol + 3][arow + i * 64] = av.w;
        }
#pragma unroll
        for (int i = 0; i < 2; i++) {
            float4 wv = *(const float4*)&W[(size_t)(kt + wrow + i * 8) * N + Ncol + wcol];
            *(float4*)&Ws[wrow + i * 8][wcol] = wv;
        }
        __syncthreads();
#pragma unroll
        for (int kk = 0; kk < 16; kk++) {
            float a[8], b[8];
#pragma unroll
            for (int i = 0; i < 8; i++) a[i] = As[kk][ty * 8 + i];
#pragma unroll
            for (int j = 0; j < 8; j++) b[j] = Ws[kk][tx * 8 + j];
#pragma unroll
            for (int i = 0; i < 8; i++)
#pragma unroll
                for (int j = 0; j < 8; j++)
                    acc[i][j] = fmaf(a[i], b[j], acc[i][j]);
        }
        __syncthreads();
    }
#pragma unroll
    for (int i = 0; i < 8; i++) {
        int m = Mrow + ty * 8 + i;
#pragma unroll
        for (int j = 0; j < 8; j++) {
            int col = Ncol + tx * 8 + j;
            out[(size_t)m * 1024 + col] = acc[i][j] + bias[col];
        }
    }
}

// ---------------- codes = pack(q @ planes > 0)  (FROZEN) ----------------
__global__ void __launch_bounds__(256) codes_kernel(const float* __restrict__ planes)
{
    __shared__ float pl[64 * 32];
    const int tid = threadIdx.x;
    for (int i = tid; i < 2048; i += 256) pl[i] = planes[i];
    __syncthreads();
    const int warp = tid / 32, lane = tid % 32;
    const int rowBase = (blockIdx.x * 8 + warp) * 16;
    for (int r = 0; r < 16; r++) {
        const int row = rowBase + r;
        const float* qrow = &g_q[(size_t)row * 64];
        float s = 0.f;
#pragma unroll
        for (int e = 0; e < 64; e++)
            s = fmaf(__ldg(&qrow[e]), pl[e * 32 + lane], s);
        unsigned w = __ballot_sync(0xffffffffu, s > 0.f);
        if (lane == 0) g_codes[row] = w;
    }
}

// ---------------- k-means: init / assign / update (integer-exact, multi-launch) ----------------
__global__ void km_init()
{
    const int b = blockIdx.x, c = threadIdx.x;
    g_cent[b * CC + c] = g_codes[b * LL + (273 * c) / 17];   // exact linspace floor
    g_histc[b * CC + c] = 0;
    g_cnt[b * CC + c] = 0;
#pragma unroll
    for (int j = 0; j < 16; j++) g_histb[(b * CC + c) * 16 + j] = 0;
}

// grid (8, 64): 512 points per block. Packed dual-16 histograms: per-head counts
// <= 4096 < 2^16, so no cross-half carry; global atomic merge is integer-exact.
__global__ void __launch_bounds__(256) km_assign(int final_pass)
{
    __shared__ unsigned scent[CC];
    __shared__ int shc[CC];
    __shared__ unsigned shb[CC * 16];
    const int b = blockIdx.y;
    const int tid = threadIdx.x;
    scent[tid] = g_cent[b * CC + tid];
    if (!final_pass) {
        shc[tid] = 0;
        for (int i = tid; i < CC * 16; i += 256) shb[i] = 0;
    }
    __syncthreads();
    const int p0 = blockIdx.x * 512;
#pragma unroll
    for (int r = 0; r < 2; r++) {
        const int p = p0 + r * 256 + tid;
        const unsigned w = g_codes[b * LL + p];
        int best = INT_MAX;
#pragma unroll 16
        for (int c = 0; c < CC; c++) {
            int d = __popc(w ^ scent[c]);
            best = min(best, (d << 8) | c);
        }
        const int bc = best & 255;
        if (final_pass) {
            g_assign[b * LL + p] = bc;
            atomicAdd(&g_cnt[b * CC + bc], 1);
        } else {
            atomicAdd(&shc[bc], 1);
#pragma unroll
            for (int j = 0; j < 16; j++) {
                unsigned contrib = ((w >> (2 * j)) & 1u) | (((w >> (2 * j + 1)) & 1u) << 16);
                if (contrib) atomicAdd(&shb[bc * 16 + j], contrib);
            }
        }
    }
    if (!final_pass) {
        __syncthreads();
        if (shc[tid]) atomicAdd(&g_histc[b * CC + tid], shc[tid]);
        for (int i = tid; i < CC * 16; i += 256) {
            unsigned v = shb[i];
            if (v) atomicAdd(&g_histb[b * CC * 16 + i], v);
        }
    }
}

__global__ void km_update()
{
    const int b = blockIdx.x, c = threadIdx.x;
    const int cnt = g_histc[b * CC + c];
    const unsigned old = g_cent[b * CC + c];
    unsigned nw = 0;
#pragma unroll
    for (int j = 0; j < 16; j++) {
        const unsigned pk = g_histb[(b * CC + c) * 16 + j];
        const int s0 = (int)(pk & 0xffffu);
        const int s1 = (int)(pk >> 16);
        if (2 * s0 >= cnt) nw |= 1u << (2 * j);
        if (2 * s1 >= cnt) nw |= 1u << (2 * j + 1);
        g_histb[(b * CC + c) * 16 + j] = 0;
    }
    g_cent[b * CC + c] = (cnt > 0) ? nw : old;
    g_histc[b * CC + c] = 0;
}

// ---------------- qc = segmented mean of q per cluster (FROZEN) ----------------
__global__ void __launch_bounds__(256) qc_kernel()
{
    __shared__ long long sq[CC * 17];
    const int b = blockIdx.y;
    const int eq = blockIdx.x * 16;
    const int tid = threadIdx.x;
    for (int i = tid; i < CC * 17; i += 256) sq[i] = 0;
    __syncthreads();
    for (int p = tid; p < LL; p += 256) {
        const int c = g_assign[b * LL + p];
        const float* q = &g_q[((size_t)(b * LL + p)) * 64 + eq];
#pragma unroll
        for (int e = 0; e < 16; e++) {
            long long v = (long long)llrintf(q[e] * 1073741824.0f);
            atomicAdd((unsigned long long*)&sq[c * 17 + e], (unsigned long long)v);
        }
    }
    __syncthreads();
    for (int i = tid; i < CC * 16; i += 256) {
        const int c = i / 16, e = i % 16;
        const float cnt = fmaxf((float)g_cnt[b * CC + c], 1.f);
        const double s = (double)sq[c * 17 + e] * (1.0 / 1073741824.0);
        g_qc[((size_t)(b * CC + c)) * 64 + eq + e] = (float)(s / (double)cnt);
    }
}

// ---------------- fused attention: vc = softmax(TEMP * qc@k^T) @ v ----------------
__global__ void __launch_bounds__(256) attn_kernel()
{
    __shared__ float qcs[64][36];
    __shared__ float kvs[64][68];
    __shared__ float ps[32][68];
    __shared__ float lsum[32];
    const int b = blockIdx.y;
    const int c0 = blockIdx.x * 32;
    const int tid = threadIdx.x;
    const int sx = tid % 16;
    const int cy = tid / 16;

    for (int i = tid; i < 32 * 16; i += 256) {
        int c = i / 16, e4 = (i % 16) * 4;
        float4 v = *(const float4*)&g_qc[((size_t)(b * CC + c0 + c)) * 64 + e4];
        qcs[e4 + 0][c] = v.x; qcs[e4 + 1][c] = v.y;
        qcs[e4 + 2][c] = v.z; qcs[e4 + 3][c] = v.w;
    }
    if (tid < 32) lsum[tid] = 0.f;

    float acc[2][4];
#pragma unroll
    for (int i = 0; i < 2; i++)
#pragma unroll
        for (int j = 0; j < 4; j++) acc[i][j] = 0.f;
    __syncthreads();

    for (int s0 = 0; s0 < LL; s0 += 64) {
        for (int i = tid; i < 64 * 16; i += 256) {
            int s = i / 16, e4 = (i % 16) * 4;
            float4 v = *(const float4*)&g_k[((size_t)(b * LL + s0 + s)) * 64 + e4];
            kvs[e4 + 0][s] = v.x; kvs[e4 + 1][s] = v.y;
            kvs[e4 + 2][s] = v.z; kvs[e4 + 3][s] = v.w;
        }
        __syncthreads();
        {
            float sc[2][4];
#pragma unroll
            for (int i = 0; i < 2; i++)
#pragma unroll
                for (int j = 0; j < 4; j++) sc[i][j] = 0.f;
            for (int e = 0; e < 64; e++) {
                float a0 = qcs[e][cy * 2 + 0];
                float a1 = qcs[e][cy * 2 + 1];
                float4 bb = *(const float4*)&kvs[e][sx * 4];
                sc[0][0] = fmaf(a0, bb.x, sc[0][0]); sc[0][1] = fmaf(a0, bb.y, sc[0][1]);
                sc[0][2] = fmaf(a0, bb.z, sc[0][2]); sc[0][3] = fmaf(a0, bb.w, sc[0][3]);
                sc[1][0] = fmaf(a1, bb.x, sc[1][0]); sc[1][1] = fmaf(a1, bb.y, sc[1][1]);
                sc[1][2] = fmaf(a1, bb.z, sc[1][2]); sc[1][3] = fmaf(a1, bb.w, sc[1][3]);
            }
#pragma unroll
            for (int i = 0; i < 2; i++)
#pragma unroll
                for (int j = 0; j < 4; j++)
                    ps[cy * 2 + i][sx * 4 + j] = __expf(sc[i][j] * TEMP_F);
        }
        __syncthreads();
        for (int i = tid; i < 64 * 16; i += 256) {
            int s = i / 16, e4 = (i % 16) * 4;
            *(float4*)&kvs[s][e4] = *(const float4*)&g_v[((size_t)(b * LL + s0 + s)) * 64 + e4];
        }
        if (tid < 32) {
            float l = 0.f;
            for (int s = 0; s < 64; s++) l += ps[tid][s];
            lsum[tid] += l;
        }
        __syncthreads();
        for (int s = 0; s < 64; s++) {
            float p0 = ps[cy * 2 + 0][s];
            float p1 = ps[cy * 2 + 1][s];
            float4 vv = *(const float4*)&kvs[s][sx * 4];
            acc[0][0] = fmaf(p0, vv.x, acc[0][0]); acc[0][1] = fmaf(p0, vv.y, acc[0][1]);
            acc[0][2] = fmaf(p0, vv.z, acc[0][2]); acc[0][3] = fmaf(p0, vv.w, acc[0][3]);
            acc[1][0] = fmaf(p1, vv.x, acc[1][0]); acc[1][1] = fmaf(p1, vv.y, acc[1][1]);
            acc[1][2] = fmaf(p1, vv.z, acc[1][2]); acc[1][3] = fmaf(p1, vv.w, acc[1][3]);
        }
        __syncthreads();
    }
#pragma unroll
    for (int i = 0; i < 2; i++) {
        const float inv = 1.f / lsum[cy * 2 + i];
#pragma unroll
        for (int j = 0; j < 4; j++)
            g_vc[((size_t)(b * CC + c0 + cy * 2 + i)) * 64 + sx * 4 + j] = acc[i][j] * inv;
    }
}

// ---------------- launch ----------------
extern "C" void kernel_launch(void* const* d_in, const int* in_sizes, int n_in,
                              void* d_out, int out_size)
{
    const float* x      = (const float*)d_in[0];
    const float* Wq     = (const float*)d_in[2];
    const float* bq     = (const float*)d_in[3];
    const float* Wk     = (const float*)d_in[4];
    const float* bk     = (const float*)d_in[5];
    const float* Wv     = (const float*)d_in[6];
    const float* bv     = (const float*)d_in[7];
    const float* Wo     = (const float*)d_in[8];
    const float* bo     = (const float*)d_in[9];
    const float* planes = (const float*)d_in[10];
    float* out = (float*)d_out;

    gemm_q<<<dim3(8, 256), 256>>>(x, Wq, bq);                 // EXACT arithmetic (restaged)
    gemm_kv<<<dim3(8, 128, 2), 256>>>(x, Wk, Wv, bk, bv);
    codes_kernel<<<2048, 256>>>(planes);                      // FROZEN
    km_init<<<64, 256>>>();
    for (int it = 0; it < KM_ITERS; it++) {
        km_assign<<<dim3(8, 64), 256>>>(0);
        km_update<<<64, 256>>>();
    }
    km_assign<<<dim3(8, 64), 256>>>(1);
    qc_kernel<<<dim3(4, 64), 256>>>();                        // FROZEN
    attn_kernel<<<dim3(8, 64), 256>>>();
    gemm_out_g<<<dim3(8, 128), 256>>>(Wo, bo, out);
}

// round 11
// speedup vs baseline: 1.5645x; 1.1726x over previous
#include <cuda_runtime.h>
#include <cuda_bf16.h>
#include <math.h>
#include <limits.h>

// Problem constants
#define NB    4
#define LL    4096
#define DD    1024
#define HH    16
#define EE    64
#define BB    64          // NB*HH
#define CC    256
#define BITS  32
#define KM_ITERS 10
#define MM    16384       // NB*LL
#define TEMP_F 0.125f

// ---------------- scratch (__device__ globals; no allocation allowed) ----------------
__device__ float    g_q[(size_t)BB * LL * EE];
__device__ float    g_k[(size_t)BB * LL * EE];
__device__ float    g_v[(size_t)BB * LL * EE];
__device__ unsigned g_codes[BB * LL];
__device__ unsigned g_cent[BB * CC];
__device__ int      g_histc[BB * CC];
__device__ unsigned g_histb[BB * CC * 16];
__device__ int      g_assign[BB * LL];
__device__ int      g_cnt[BB * CC];
__device__ float    g_qc[(size_t)BB * CC * EE];
__device__ float    g_vc[(size_t)BB * CC * EE];

// ---------------- tf32 split helpers ----------------
__device__ __forceinline__ void split_tf32(float x, unsigned &hi, unsigned &lo)
{
    unsigned h;
    asm("cvt.rna.tf32.f32 %0, %1;" : "=r"(h) : "f"(x));
    float l = x - __uint_as_float(h);
    unsigned l32;
    asm("cvt.rna.tf32.f32 %0, %1;" : "=r"(l32) : "f"(l));
    hi = h; lo = l32;
}

__device__ __forceinline__ void mma_tf32(float c[4],
                                         unsigned a0, unsigned a1, unsigned a2, unsigned a3,
                                         unsigned b0, unsigned b1)
{
    asm volatile(
        "mma.sync.aligned.m16n8k8.row.col.f32.tf32.tf32.f32 "
        "{%0,%1,%2,%3}, {%4,%5,%6,%7}, {%8,%9}, {%0,%1,%2,%3};\n"
        : "+f"(c[0]), "+f"(c[1]), "+f"(c[2]), "+f"(c[3])
        : "r"(a0), "r"(a1), "r"(a2), "r"(a3), "r"(b0), "r"(b1));
}

// =============== EXACT q GEMM (FROZEN — Eigen gebp, KC=248 panels) ===============
__global__ void __launch_bounds__(256) gemm_q(const float* __restrict__ A,
                                              const float* __restrict__ W,
                                              const float* __restrict__ bias)
{
    const int K = 1024, N = 1024;
    const int Mrow = blockIdx.y * 64;
    const int Ncol = blockIdx.x * 128;
    __shared__ float As[32][68];
    __shared__ float Ws[32][132];
    const int tid = threadIdx.x;
    const int tx = tid % 16, ty = tid / 16;
    const int arow = tid / 4;
    const int acol = (tid % 4) * 8;
    const int wrow = tid / 32;
    const int wcol = (tid % 32) * 4;

    float c_[4][8], t_[4][8];
#pragma unroll
    for (int i = 0; i < 4; i++)
#pragma unroll
        for (int j = 0; j < 8; j++) { c_[i][j] = 0.f; t_[i][j] = 0.f; }

    for (int kt = 0; kt < K; kt += 32) {
        {
            const float* arow_p = &A[(size_t)(Mrow + arow) * K + kt + acol];
            float4 a0 = *(const float4*)&arow_p[0];
            float4 a1 = *(const float4*)&arow_p[4];
            As[acol + 0][arow] = a0.x; As[acol + 1][arow] = a0.y;
            As[acol + 2][arow] = a0.z; As[acol + 3][arow] = a0.w;
            As[acol + 4][arow] = a1.x; As[acol + 5][arow] = a1.y;
            As[acol + 6][arow] = a1.z; As[acol + 7][arow] = a1.w;
        }
#pragma unroll
        for (int r = 0; r < 4; r++) {
            float4 wv = *(const float4*)&W[(size_t)(kt + wrow + r * 8) * N + Ncol + wcol];
            *(float4*)&Ws[wrow + r * 8][wcol] = wv;
        }
        __syncthreads();
#pragma unroll
        for (int g = 0; g < 4; g++) {
#pragma unroll
            for (int kk8 = 0; kk8 < 8; kk8++) {
                const int kk = g * 8 + kk8;
                float4 av = *(const float4*)&As[kk][ty * 4];
                float4 b0 = *(const float4*)&Ws[kk][tx * 8];
                float4 b1 = *(const float4*)&Ws[kk][tx * 8 + 4];
                float a[4] = {av.x, av.y, av.z, av.w};
                float b[8] = {b0.x, b0.y, b0.z, b0.w, b1.x, b1.y, b1.z, b1.w};
#pragma unroll
                for (int i = 0; i < 4; i++)
#pragma unroll
                    for (int j = 0; j < 8; j++)
                        t_[i][j] = fmaf(a[i], b[j], t_[i][j]);
            }
            const int kend = kt + g * 8 + 8;
            if (kend == 248 || kend == 496 || kend == 744 || kend == 992 || kend == 1024) {
#pragma unroll
                for (int i = 0; i < 4; i++)
#pragma unroll
                    for (int j = 0; j < 8; j++) {
                        c_[i][j] = __fadd_rn(c_[i][j], t_[i][j]);
                        t_[i][j] = 0.f;
                    }
            }
        }
        __syncthreads();
    }
#pragma unroll
    for (int i = 0; i < 4; i++) {
        int m = Mrow + ty * 4 + i;
#pragma unroll
        for (int j = 0; j < 8; j++) {
            int col = Ncol + tx * 8 + j;
            float val = c_[i][j] + bias[col];
            int n = m >> 12, l = m & 4095, h = col >> 6, e = col & 63;
            g_q[(((size_t)(n * 16 + h)) * 4096 + l) * 64 + e] = val;
        }
    }
}

// =============== 3xTF32 tensor-core GEMM (continuous paths) ===============
// MODE 0: A from global (x), output remapped to [b][l][e]  (k/v projections)
// MODE 1: A gathered from g_vc via g_assign, plain row-major output (out GEMM)
template<int MODE>
__device__ __forceinline__ void tf32_gemm_body(const float* __restrict__ A,
                                               const float* __restrict__ W,
                                               const float* __restrict__ bias,
                                               float* __restrict__ out)
{
    const int K = 1024, N = 1024;
    const int Mrow = blockIdx.y * 128;
    const int Ncol = blockIdx.x * 128;
    __shared__ float As[16][136];   // [k][m]
    __shared__ float Ws[16][132];   // [k][n]
    const int tid = threadIdx.x;
    const int warp = tid >> 5, lane = tid & 31;
    const int grp = lane >> 2, tig = lane & 3;
    const int wm = (warp & 3) * 32;     // warp m offset within tile
    const int wn = (warp >> 2) * 64;    // warp n offset within tile

    float acc[2][8][4];
#pragma unroll
    for (int tm = 0; tm < 2; tm++)
#pragma unroll
        for (int tn = 0; tn < 8; tn++)
#pragma unroll
            for (int r = 0; r < 4; r++) acc[tm][tn][r] = 0.f;

    for (int kt = 0; kt < K; kt += 16) {
        // A tile: 128 rows x 16 k
        {
            const int r = tid >> 2;
            const int kc = (tid & 3) * 4;
#pragma unroll
            for (int i = 0; i < 2; i++) {
                const int m = Mrow + r + i * 64;
                float4 av;
                if (MODE == 1) {
                    const int col = kt + kc;
                    const int n_ = m >> 12, l = m & 4095;
                    const int h = col >> 6, e4 = col & 63;
                    const int b = n_ * 16 + h;
                    const int c = g_assign[b * LL + l];
                    av = *(const float4*)&g_vc[((size_t)(b * CC + c)) * 64 + e4];
                } else {
                    av = *(const float4*)&A[(size_t)m * K + kt + kc];
                }
                As[kc + 0][r + i * 64] = av.x;
                As[kc + 1][r + i * 64] = av.y;
                As[kc + 2][r + i * 64] = av.z;
                As[kc + 3][r + i * 64] = av.w;
            }
        }
        // W tile: 16 k x 128 n
        {
            const int kr = tid >> 5;
            const int nc = (tid & 31) * 4;
#pragma unroll
            for (int i = 0; i < 2; i++) {
                float4 wv = *(const float4*)&W[(size_t)(kt + kr + i * 8) * N + Ncol + nc];
                *(float4*)&Ws[kr + i * 8][nc] = wv;
            }
        }
        __syncthreads();
#pragma unroll
        for (int ks = 0; ks < 2; ks++) {
            const int k0 = ks * 8;
            unsigned ah[2][4], al[2][4];
#pragma unroll
            for (int tm = 0; tm < 2; tm++) {
                split_tf32(As[k0 + tig    ][wm + tm * 16 + grp    ], ah[tm][0], al[tm][0]);
                split_tf32(As[k0 + tig    ][wm + tm * 16 + grp + 8], ah[tm][1], al[tm][1]);
                split_tf32(As[k0 + tig + 4][wm + tm * 16 + grp    ], ah[tm][2], al[tm][2]);
                split_tf32(As[k0 + tig + 4][wm + tm * 16 + grp + 8], ah[tm][3], al[tm][3]);
            }
#pragma unroll
            for (int tn = 0; tn < 8; tn++) {
                unsigned bh0, bl0, bh1, bl1;
                split_tf32(Ws[k0 + tig    ][wn + tn * 8 + grp], bh0, bl0);
                split_tf32(Ws[k0 + tig + 4][wn + tn * 8 + grp], bh1, bl1);
#pragma unroll
                for (int tm = 0; tm < 2; tm++) {
                    mma_tf32(acc[tm][tn], ah[tm][0], ah[tm][1], ah[tm][2], ah[tm][3], bh0, bh1);
                    mma_tf32(acc[tm][tn], ah[tm][0], ah[tm][1], ah[tm][2], ah[tm][3], bl0, bl1);
                    mma_tf32(acc[tm][tn], al[tm][0], al[tm][1], al[tm][2], al[tm][3], bh0, bh1);
                }
            }
        }
        __syncthreads();
    }
    // epilogue
#pragma unroll
    for (int tm = 0; tm < 2; tm++) {
#pragma unroll
        for (int tn = 0; tn < 8; tn++) {
#pragma unroll
            for (int r = 0; r < 2; r++) {
                const int m = Mrow + wm + tm * 16 + grp + r * 8;
                const int n = Ncol + wn + tn * 8 + tig * 2;
                const float v0 = acc[tm][tn][r * 2 + 0] + bias[n];
                const float v1 = acc[tm][tn][r * 2 + 1] + bias[n + 1];
                if (MODE == 0) {
                    const int nb = m >> 12, l = m & 4095;
                    const int h = n >> 6, e = n & 63;   // n,n+1 same head (n even)
                    float* p = &out[(((size_t)(nb * 16 + h)) * 4096 + l) * 64 + e];
                    p[0] = v0; p[1] = v1;
                } else {
                    out[(size_t)m * 1024 + n] = v0;
                    out[(size_t)m * 1024 + n + 1] = v1;
                }
            }
        }
    }
}

__global__ void __launch_bounds__(256) gemm_kv(const float* __restrict__ A,
                                               const float* __restrict__ Wk,
                                               const float* __restrict__ Wv,
                                               const float* __restrict__ bk,
                                               const float* __restrict__ bv)
{
    if (blockIdx.z == 0) tf32_gemm_body<0>(A, Wk, bk, g_k);
    else                 tf32_gemm_body<0>(A, Wv, bv, g_v);
}

__global__ void __launch_bounds__(256) gemm_out_g(const float* __restrict__ W,
                                                  const float* __restrict__ bias,
                                                  float* __restrict__ out)
{
    tf32_gemm_body<1>(nullptr, W, bias, out);
}

// ---------------- codes = pack(q @ planes > 0)  (FROZEN) ----------------
__global__ void __launch_bounds__(256) codes_kernel(const float* __restrict__ planes)
{
    __shared__ float pl[64 * 32];
    const int tid = threadIdx.x;
    for (int i = tid; i < 2048; i += 256) pl[i] = planes[i];
    __syncthreads();
    const int warp = tid / 32, lane = tid % 32;
    const int rowBase = (blockIdx.x * 8 + warp) * 16;
    for (int r = 0; r < 16; r++) {
        const int row = rowBase + r;
        const float* qrow = &g_q[(size_t)row * 64];
        float s = 0.f;
#pragma unroll
        for (int e = 0; e < 64; e++)
            s = fmaf(__ldg(&qrow[e]), pl[e * 32 + lane], s);
        unsigned w = __ballot_sync(0xffffffffu, s > 0.f);
        if (lane == 0) g_codes[row] = w;
    }
}

// ---------------- k-means: init / assign / update (FROZEN, integer-exact) ----------------
__global__ void km_init()
{
    const int b = blockIdx.x, c = threadIdx.x;
    g_cent[b * CC + c] = g_codes[b * LL + (273 * c) / 17];
    g_histc[b * CC + c] = 0;
    g_cnt[b * CC + c] = 0;
#pragma unroll
    for (int j = 0; j < 16; j++) g_histb[(b * CC + c) * 16 + j] = 0;
}

__global__ void __launch_bounds__(256) km_assign(int final_pass)
{
    __shared__ unsigned scent[CC];
    __shared__ int shc[CC];
    __shared__ unsigned shb[CC * 16];
    const int b = blockIdx.y;
    const int tid = threadIdx.x;
    scent[tid] = g_cent[b * CC + tid];
    if (!final_pass) {
        shc[tid] = 0;
        for (int i = tid; i < CC * 16; i += 256) shb[i] = 0;
    }
    __syncthreads();
    const int p0 = blockIdx.x * 512;
#pragma unroll
    for (int r = 0; r < 2; r++) {
        const int p = p0 + r * 256 + tid;
        const unsigned w = g_codes[b * LL + p];
        int best = INT_MAX;
#pragma unroll 16
        for (int c = 0; c < CC; c++) {
            int d = __popc(w ^ scent[c]);
            best = min(best, (d << 8) | c);
        }
        const int bc = best & 255;
        if (final_pass) {
            g_assign[b * LL + p] = bc;
            atomicAdd(&g_cnt[b * CC + bc], 1);
        } else {
            atomicAdd(&shc[bc], 1);
#pragma unroll
            for (int j = 0; j < 16; j++) {
                unsigned contrib = ((w >> (2 * j)) & 1u) | (((w >> (2 * j + 1)) & 1u) << 16);
                if (contrib) atomicAdd(&shb[bc * 16 + j], contrib);
            }
        }
    }
    if (!final_pass) {
        __syncthreads();
        if (shc[tid]) atomicAdd(&g_histc[b * CC + tid], shc[tid]);
        for (int i = tid; i < CC * 16; i += 256) {
            unsigned v = shb[i];
            if (v) atomicAdd(&g_histb[b * CC * 16 + i], v);
        }
    }
}

__global__ void km_update()
{
    const int b = blockIdx.x, c = threadIdx.x;
    const int cnt = g_histc[b * CC + c];
    const unsigned old = g_cent[b * CC + c];
    unsigned nw = 0;
#pragma unroll
    for (int j = 0; j < 16; j++) {
        const unsigned pk = g_histb[(b * CC + c) * 16 + j];
        const int s0 = (int)(pk & 0xffffu);
        const int s1 = (int)(pk >> 16);
        if (2 * s0 >= cnt) nw |= 1u << (2 * j);
        if (2 * s1 >= cnt) nw |= 1u << (2 * j + 1);
        g_histb[(b * CC + c) * 16 + j] = 0;
    }
    g_cent[b * CC + c] = (cnt > 0) ? nw : old;
    g_histc[b * CC + c] = 0;
}

// ---------------- qc = segmented mean of q per cluster (FROZEN) ----------------
__global__ void __launch_bounds__(256) qc_kernel()
{
    __shared__ long long sq[CC * 17];
    const int b = blockIdx.y;
    const int eq = blockIdx.x * 16;
    const int tid = threadIdx.x;
    for (int i = tid; i < CC * 17; i += 256) sq[i] = 0;
    __syncthreads();
    for (int p = tid; p < LL; p += 256) {
        const int c = g_assign[b * LL + p];
        const float* q = &g_q[((size_t)(b * LL + p)) * 64 + eq];
#pragma unroll
        for (int e = 0; e < 16; e++) {
            long long v = (long long)llrintf(q[e] * 1073741824.0f);
            atomicAdd((unsigned long long*)&sq[c * 17 + e], (unsigned long long)v);
        }
    }
    __syncthreads();
    for (int i = tid; i < CC * 16; i += 256) {
        const int c = i / 16, e = i % 16;
        const float cnt = fmaxf((float)g_cnt[b * CC + c], 1.f);
        const double s = (double)sq[c * 17 + e] * (1.0 / 1073741824.0);
        g_qc[((size_t)(b * CC + c)) * 64 + eq + e] = (float)(s / (double)cnt);
    }
}

// ---------------- fused attention: vc = softmax(TEMP * qc@k^T) @ v ----------------
__global__ void __launch_bounds__(256) attn_kernel()
{
    __shared__ float qcs[64][36];
    __shared__ float kvs[64][68];
    __shared__ float ps[32][68];
    __shared__ float lsum[32];
    const int b = blockIdx.y;
    const int c0 = blockIdx.x * 32;
    const int tid = threadIdx.x;
    const int sx = tid % 16;
    const int cy = tid / 16;

    for (int i = tid; i < 32 * 16; i += 256) {
        int c = i / 16, e4 = (i % 16) * 4;
        float4 v = *(const float4*)&g_qc[((size_t)(b * CC + c0 + c)) * 64 + e4];
        qcs[e4 + 0][c] = v.x; qcs[e4 + 1][c] = v.y;
        qcs[e4 + 2][c] = v.z; qcs[e4 + 3][c] = v.w;
    }
    if (tid < 32) lsum[tid] = 0.f;

    float acc[2][4];
#pragma unroll
    for (int i = 0; i < 2; i++)
#pragma unroll
        for (int j = 0; j < 4; j++) acc[i][j] = 0.f;
    __syncthreads();

    for (int s0 = 0; s0 < LL; s0 += 64) {
        for (int i = tid; i < 64 * 16; i += 256) {
            int s = i / 16, e4 = (i % 16) * 4;
            float4 v = *(const float4*)&g_k[((size_t)(b * LL + s0 + s)) * 64 + e4];
            kvs[e4 + 0][s] = v.x; kvs[e4 + 1][s] = v.y;
            kvs[e4 + 2][s] = v.z; kvs[e4 + 3][s] = v.w;
        }
        __syncthreads();
        {
            float sc[2][4];
#pragma unroll
            for (int i = 0; i < 2; i++)
#pragma unroll
                for (int j = 0; j < 4; j++) sc[i][j] = 0.f;
            for (int e = 0; e < 64; e++) {
                float a0 = qcs[e][cy * 2 + 0];
                float a1 = qcs[e][cy * 2 + 1];
                float4 bb = *(const float4*)&kvs[e][sx * 4];
                sc[0][0] = fmaf(a0, bb.x, sc[0][0]); sc[0][1] = fmaf(a0, bb.y, sc[0][1]);
                sc[0][2] = fmaf(a0, bb.z, sc[0][2]); sc[0][3] = fmaf(a0, bb.w, sc[0][3]);
                sc[1][0] = fmaf(a1, bb.x, sc[1][0]); sc[1][1] = fmaf(a1, bb.y, sc[1][1]);
                sc[1][2] = fmaf(a1, bb.z, sc[1][2]); sc[1][3] = fmaf(a1, bb.w, sc[1][3]);
            }
#pragma unroll
            for (int i = 0; i < 2; i++)
#pragma unroll
                for (int j = 0; j < 4; j++)
                    ps[cy * 2 + i][sx * 4 + j] = __expf(sc[i][j] * TEMP_F);
        }
        __syncthreads();
        for (int i = tid; i < 64 * 16; i += 256) {
            int s = i / 16, e4 = (i % 16) * 4;
            *(float4*)&kvs[s][e4] = *(const float4*)&g_v[((size_t)(b * LL + s0 + s)) * 64 + e4];
        }
        if (tid < 32) {
            float l = 0.f;
            for (int s = 0; s < 64; s++) l += ps[tid][s];
            lsum[tid] += l;
        }
        __syncthreads();
        for (int s = 0; s < 64; s++) {
            float p0 = ps[cy * 2 + 0][s];
            float p1 = ps[cy * 2 + 1][s];
            float4 vv = *(const float4*)&kvs[s][sx * 4];
            acc[0][0] = fmaf(p0, vv.x, acc[0][0]); acc[0][1] = fmaf(p0, vv.y, acc[0][1]);
            acc[0][2] = fmaf(p0, vv.z, acc[0][2]); acc[0][3] = fmaf(p0, vv.w, acc[0][3]);
            acc[1][0] = fmaf(p1, vv.x, acc[1][0]); acc[1][1] = fmaf(p1, vv.y, acc[1][1]);
            acc[1][2] = fmaf(p1, vv.z, acc[1][2]); acc[1][3] = fmaf(p1, vv.w, acc[1][3]);
        }
        __syncthreads();
    }
#pragma unroll
    for (int i = 0; i < 2; i++) {
        const float inv = 1.f / lsum[cy * 2 + i];
#pragma unroll
        for (int j = 0; j < 4; j++)
            g_vc[((size_t)(b * CC + c0 + cy * 2 + i)) * 64 + sx * 4 + j] = acc[i][j] * inv;
    }
}

// ---------------- launch ----------------
extern "C" void kernel_launch(void* const* d_in, const int* in_sizes, int n_in,
                              void* d_out, int out_size)
{
    const float* x      = (const float*)d_in[0];
    const float* Wq     = (const float*)d_in[2];
    const float* bq     = (const float*)d_in[3];
    const float* Wk     = (const float*)d_in[4];
    const float* bk     = (const float*)d_in[5];
    const float* Wv     = (const float*)d_in[6];
    const float* bv     = (const float*)d_in[7];
    const float* Wo     = (const float*)d_in[8];
    const float* bo     = (const float*)d_in[9];
    const float* planes = (const float*)d_in[10];
    float* out = (float*)d_out;

    gemm_q<<<dim3(8, 256), 256>>>(x, Wq, bq);                 // EXACT (frozen)
    gemm_kv<<<dim3(8, 128, 2), 256>>>(x, Wk, Wv, bk, bv);     // 3xTF32 tensor
    codes_kernel<<<2048, 256>>>(planes);                      // FROZEN
    km_init<<<64, 256>>>();
    for (int it = 0; it < KM_ITERS; it++) {
        km_assign<<<dim3(8, 64), 256>>>(0);
        km_update<<<64, 256>>>();
    }
    km_assign<<<dim3(8, 64), 256>>>(1);
    qc_kernel<<<dim3(4, 64), 256>>>();                        // FROZEN
    attn_kernel<<<dim3(8, 64), 256>>>();
    gemm_out_g<<<dim3(8, 128), 256>>>(Wo, bo, out);           // 3xTF32 tensor + gather
}